// round 1
// baseline (speedup 1.0000x reference)
#include <cuda_runtime.h>
#include <cstddef>

#define NG 50000
#define ND 20000
#define HD 128
#define EGG 800000
#define EGDA 400000
#define ELAB 200000

// ---------------- scratch (static device arrays; no runtime allocation) ----------------
__device__ float d_agg_gg[(size_t)NG * HD];
__device__ float d_agg_rev[(size_t)NG * HD];
__device__ float d_agg_d[(size_t)ND * HD];
__device__ float d_g1[(size_t)NG * HD];
__device__ float d_d1[(size_t)ND * HD];
__device__ float d_g2[(size_t)NG * HD];
__device__ float d_d2[(size_t)ND * HD];
__device__ float d_rdeg_gg[NG];
__device__ float d_rdeg_rev[NG];
__device__ float d_rdeg_d[ND];
// combined weights per layer: gene path (3 terms, 0.5 folded in), disease path (2 terms)
__device__ float d_WgX[2][HD * HD];
__device__ float d_WgA[2][HD * HD];
__device__ float d_WgR[2][HD * HD];
__device__ float d_WdX[2][HD * HD];
__device__ float d_WdA[2][HD * HD];
__device__ float d_bg[2][HD];
__device__ float d_bd[2][HD];
__device__ float d_bn_sum[2 * HD];
__device__ float d_bn_sumsq[2 * HD];
__device__ float d_bn_scale[2][HD];
__device__ float d_bn_shift[2][HD];

// ---------------- utility kernels ----------------
__global__ void zero4_kernel(float4* p, int n4) {
    int i = blockIdx.x * blockDim.x + threadIdx.x;
    if (i < n4) p[i] = make_float4(0.f, 0.f, 0.f, 0.f);
}

__global__ void deg_kernel(const int* __restrict__ dst, int nE, float* __restrict__ deg) {
    int i = blockIdx.x * blockDim.x + threadIdx.x;
    if (i < nE) atomicAdd(&deg[dst[i]], 1.0f);
}

__global__ void rdeg_kernel(float* __restrict__ d, int n) {
    int i = blockIdx.x * blockDim.x + threadIdx.x;
    if (i < n) d[i] = 1.0f / fmaxf(d[i], 1.0f);
}

// scatter-add: one thread per (edge, float4 chunk); vector red to L2
__global__ void scatter_kernel(const float* __restrict__ X, const int* __restrict__ src,
                               const int* __restrict__ dst, int nE, float* __restrict__ agg) {
    int i = blockIdx.x * blockDim.x + threadIdx.x;
    int e = i >> 5;
    int q = i & 31;
    if (e >= nE) return;
    int s = __ldg(&src[e]);
    int d0 = __ldg(&dst[e]);
    float4 v = *(const float4*)&X[(size_t)s * HD + q * 4];
    float* p = &agg[(size_t)d0 * HD + q * 4];
    asm volatile("red.global.add.v4.f32 [%0], {%1, %2, %3, %4};"
                 :: "l"(p), "f"(v.x), "f"(v.y), "f"(v.z), "f"(v.w) : "memory");
}

// ---------------- fused multi-term SGEMM ----------------
// out[m][h] = post_scale * sum_t ( (r_t ? r_t[m] : 1) * X_t[m][:] ) @ W_t[:][h]  + bias[h]
// X_t: [n x 128] row-major, W_t: [128 x 128] row-major. Up to 3 terms (X==nullptr skips).
__global__ __launch_bounds__(256) void fgemm_kernel(
    const float* __restrict__ X0, const float* __restrict__ W0, const float* __restrict__ r0,
    const float* __restrict__ X1, const float* __restrict__ W1, const float* __restrict__ r1,
    const float* __restrict__ X2, const float* __restrict__ W2, const float* __restrict__ r2,
    const float* __restrict__ bias, float post_scale, float* __restrict__ out, int n) {
    __shared__ __align__(16) float Xs[16][132];
    __shared__ __align__(16) float Ws[16][128];
    int tid = threadIdx.x;
    int m0 = blockIdx.x * 128;
    float acc[8][8];
#pragma unroll
    for (int i = 0; i < 8; ++i)
#pragma unroll
        for (int j = 0; j < 8; ++j) acc[i][j] = 0.f;

    const float* Xp[3] = {X0, X1, X2};
    const float* Wp[3] = {W0, W1, W2};
    const float* rp[3] = {r0, r1, r2};

    int rA = tid >> 2;    // 0..63  (X-tile row group)
    int kq = tid & 3;     // 0..3   (X-tile k quad)
    int krow = tid >> 4;  // 0..15  (W-tile row)
    int cq = tid & 15;    // 0..15  (W-tile col quad)
    int tx = tid & 15;
    int ty = tid >> 4;

    for (int t = 0; t < 3; ++t) {
        const float* X = Xp[t];
        if (!X) continue;
        const float* W = Wp[t];
        const float* rs = rp[t];
        for (int kc = 0; kc < 8; ++kc) {
            // load X tile (128 rows x 16 k), transposed into Xs[k][m], row-scaled
#pragma unroll
            for (int h = 0; h < 2; ++h) {
                int r = rA + h * 64;
                int gm = m0 + r;
                float4 v = make_float4(0.f, 0.f, 0.f, 0.f);
                if (gm < n) {
                    v = *(const float4*)&X[(size_t)gm * 128 + kc * 16 + kq * 4];
                    if (rs) {
                        float sc = __ldg(&rs[gm]);
                        v.x *= sc; v.y *= sc; v.z *= sc; v.w *= sc;
                    }
                }
                Xs[kq * 4 + 0][r] = v.x;
                Xs[kq * 4 + 1][r] = v.y;
                Xs[kq * 4 + 2][r] = v.z;
                Xs[kq * 4 + 3][r] = v.w;
            }
            // load W tile (16 k-rows x 128 cols)
#pragma unroll
            for (int h = 0; h < 2; ++h) {
                int c = cq + h * 16;
                *(float4*)&Ws[krow][c * 4] = *(const float4*)&W[(size_t)(kc * 16 + krow) * 128 + c * 4];
            }
            __syncthreads();
#pragma unroll
            for (int k = 0; k < 16; ++k) {
                float a[8], b[8];
                *(float4*)&a[0] = *(const float4*)&Xs[k][ty * 8];
                *(float4*)&a[4] = *(const float4*)&Xs[k][ty * 8 + 4];
                *(float4*)&b[0] = *(const float4*)&Ws[k][tx * 8];
                *(float4*)&b[4] = *(const float4*)&Ws[k][tx * 8 + 4];
#pragma unroll
                for (int i = 0; i < 8; ++i)
#pragma unroll
                    for (int j = 0; j < 8; ++j) acc[i][j] = fmaf(a[i], b[j], acc[i][j]);
            }
            __syncthreads();
        }
    }
    // epilogue
#pragma unroll
    for (int i = 0; i < 8; ++i) {
        int gm = m0 + ty * 8 + i;
        if (gm >= n) continue;
        float4 o0, o1;
        int c = tx * 8;
        o0.x = acc[i][0] * post_scale; o0.y = acc[i][1] * post_scale;
        o0.z = acc[i][2] * post_scale; o0.w = acc[i][3] * post_scale;
        o1.x = acc[i][4] * post_scale; o1.y = acc[i][5] * post_scale;
        o1.z = acc[i][6] * post_scale; o1.w = acc[i][7] * post_scale;
        if (bias) {
            o0.x += __ldg(&bias[c + 0]); o0.y += __ldg(&bias[c + 1]);
            o0.z += __ldg(&bias[c + 2]); o0.w += __ldg(&bias[c + 3]);
            o1.x += __ldg(&bias[c + 4]); o1.y += __ldg(&bias[c + 5]);
            o1.z += __ldg(&bias[c + 6]); o1.w += __ldg(&bias[c + 7]);
        }
        *(float4*)&out[(size_t)gm * 128 + c] = o0;
        *(float4*)&out[(size_t)gm * 128 + c + 4] = o1;
    }
}

// ---------------- bias combine ----------------
// c_i(h) = sum_k bd[i][k]*Wu[i][k][h] + sum_k bs[i][k]*Wu[i][128+k][h] + bu[i][h]
// gene: 0.5*(c_0 + c_2)   disease: c_1
__global__ void bias_combine_kernel(const float* __restrict__ bd1, const float* __restrict__ bs1,
                                    const float* __restrict__ bu1, const float* __restrict__ Wu1,
                                    const float* __restrict__ bd2, const float* __restrict__ bs2,
                                    const float* __restrict__ bu2, const float* __restrict__ Wu2) {
    int layer = blockIdx.x >> 1;
    int which = blockIdx.x & 1;  // 0 = gene, 1 = disease
    int h = threadIdx.x;
    const float* bd = layer ? bd2 : bd1;
    const float* bs = layer ? bs2 : bs1;
    const float* bu = layer ? bu2 : bu1;
    const float* Wu = layer ? Wu2 : Wu1;
    auto cfun = [&](int i) {
        float s = bu[i * 128 + h];
        const float* wt = Wu + (size_t)i * 32768;
        for (int k = 0; k < 128; ++k) s = fmaf(bd[i * 128 + k], wt[k * 128 + h], s);
        const float* wb = wt + 16384;
        for (int k = 0; k < 128; ++k) s = fmaf(bs[i * 128 + k], wb[k * 128 + h], s);
        return s;
    };
    if (which == 0)
        d_bg[layer][h] = 0.5f * (cfun(0) + cfun(2));
    else
        d_bd[layer][h] = cfun(1);
}

// ---------------- batch norm ----------------
__global__ void bn_stats_kernel(const float* __restrict__ x, int n,
                                float* __restrict__ sum, float* __restrict__ sumsq) {
    int c = threadIdx.x;  // 128 threads
    int r0 = blockIdx.x * 128;
    int rend = min(r0 + 128, n);
    float s = 0.f, s2 = 0.f;
    for (int r = r0; r < rend; ++r) {
        float v = x[(size_t)r * 128 + c];
        s += v;
        s2 = fmaf(v, v, s2);
    }
    atomicAdd(&sum[c], s);
    atomicAdd(&sumsq[c], s2);
}

__global__ void bn_final_kernel(const float* __restrict__ gamma, const float* __restrict__ beta) {
    int idx = blockIdx.x;  // 0 = gene, 1 = disease
    int c = threadIdx.x;
    float nn = (idx == 0) ? (float)NG : (float)ND;
    float mean = d_bn_sum[idx * 128 + c] / nn;
    float var = d_bn_sumsq[idx * 128 + c] / nn - mean * mean;
    float sc = gamma[idx * 128 + c] * rsqrtf(var + 1e-5f);
    d_bn_scale[idx][c] = sc;
    d_bn_shift[idx][c] = beta[idx * 128 + c] - mean * sc;
}

__global__ void bn_apply_kernel(float* __restrict__ x, int n, int which) {
    int i = blockIdx.x * blockDim.x + threadIdx.x;  // over n*32 float4
    if (i >= n * 32) return;
    int q = i & 31;
    int c = q * 4;
    const float* sc = d_bn_scale[which];
    const float* sh = d_bn_shift[which];
    float4 v = *(float4*)&x[(size_t)i * 4];
    v.x = fmaf(v.x, sc[c + 0], sh[c + 0]);
    v.y = fmaf(v.y, sc[c + 1], sh[c + 1]);
    v.z = fmaf(v.z, sc[c + 2], sh[c + 2]);
    v.w = fmaf(v.w, sc[c + 3], sh[c + 3]);
    v.x = v.x >= 0.f ? v.x : 0.01f * v.x;
    v.y = v.y >= 0.f ? v.y : 0.01f * v.y;
    v.z = v.z >= 0.f ? v.z : 0.01f * v.z;
    v.w = v.w >= 0.f ? v.w : 0.01f * v.w;
    *(float4*)&x[(size_t)i * 4] = v;
}

// ---------------- decoder ----------------
__global__ void decode_kernel(const int* __restrict__ ls, const int* __restrict__ ld,
                              float* __restrict__ out) {
    int gw = (blockIdx.x * blockDim.x + threadIdx.x) >> 5;
    int lane = threadIdx.x & 31;
    if (gw >= ELAB) return;
    int a = __ldg(&ls[gw]);
    int b = __ldg(&ld[gw]);
    float4 u = *(const float4*)&d_g2[(size_t)a * 128 + lane * 4];
    float4 v = *(const float4*)&d_d2[(size_t)b * 128 + lane * 4];
    float s = u.x * v.x + u.y * v.y + u.z * v.z + u.w * v.w;
#pragma unroll
    for (int o = 16; o; o >>= 1) s += __shfl_xor_sync(0xFFFFFFFFu, s, o);
    if (lane == 0) out[gw] = s;
}

// ---------------- launch ----------------
static inline int cdiv(int a, int b) { return (a + b - 1) / b; }

extern "C" void kernel_launch(void* const* d_in, const int* in_sizes, int n_in,
                              void* d_out, int out_size) {
    const float* x_gene = (const float*)d_in[0];
    const float* x_dis  = (const float*)d_in[1];
    const float* W_dst1 = (const float*)d_in[2];
    const float* W_src1 = (const float*)d_in[3];
    const float* W_upd1 = (const float*)d_in[4];
    const float* b_dst1 = (const float*)d_in[5];
    const float* b_src1 = (const float*)d_in[6];
    const float* b_upd1 = (const float*)d_in[7];
    const float* W_dst2 = (const float*)d_in[8];
    const float* W_src2 = (const float*)d_in[9];
    const float* W_upd2 = (const float*)d_in[10];
    const float* b_dst2 = (const float*)d_in[11];
    const float* b_src2 = (const float*)d_in[12];
    const float* b_upd2 = (const float*)d_in[13];
    const float* bn_gamma = (const float*)d_in[14];
    const float* bn_beta  = (const float*)d_in[15];
    const int* gg_src  = (const int*)d_in[16];
    const int* gg_dst  = (const int*)d_in[17];
    const int* gda_src = (const int*)d_in[18];
    const int* gda_dst = (const int*)d_in[19];
    const int* label_src = (const int*)d_in[20];
    const int* label_dst = (const int*)d_in[21];
    float* out = (float*)d_out;

    float *agg_gg, *agg_rev, *agg_d, *g1, *d1, *g2, *d2, *rdgg, *rdrev, *rdd;
    float *WgX, *WgA, *WgR, *WdX, *WdA, *bg, *bd, *bnsum, *bnsumsq;
    cudaGetSymbolAddress((void**)&agg_gg, d_agg_gg);
    cudaGetSymbolAddress((void**)&agg_rev, d_agg_rev);
    cudaGetSymbolAddress((void**)&agg_d, d_agg_d);
    cudaGetSymbolAddress((void**)&g1, d_g1);
    cudaGetSymbolAddress((void**)&d1, d_d1);
    cudaGetSymbolAddress((void**)&g2, d_g2);
    cudaGetSymbolAddress((void**)&d2, d_d2);
    cudaGetSymbolAddress((void**)&rdgg, d_rdeg_gg);
    cudaGetSymbolAddress((void**)&rdrev, d_rdeg_rev);
    cudaGetSymbolAddress((void**)&rdd, d_rdeg_d);
    cudaGetSymbolAddress((void**)&WgX, d_WgX);
    cudaGetSymbolAddress((void**)&WgA, d_WgA);
    cudaGetSymbolAddress((void**)&WgR, d_WgR);
    cudaGetSymbolAddress((void**)&WdX, d_WdX);
    cudaGetSymbolAddress((void**)&WdA, d_WdA);
    cudaGetSymbolAddress((void**)&bg, d_bg);
    cudaGetSymbolAddress((void**)&bd, d_bd);
    cudaGetSymbolAddress((void**)&bnsum, d_bn_sum);
    cudaGetSymbolAddress((void**)&bnsumsq, d_bn_sumsq);

    const int MM = 16384;  // 128*128 matrix stride
    const int WU = 32768;  // W_upd per-relation stride (256*128)
    const int WUB = 16384; // bottom-half offset within W_upd[i]

    // ---- degrees (edge-structure only; shared by both layers) ----
    zero4_kernel<<<cdiv(NG / 4, 256), 256>>>((float4*)rdgg, NG / 4);
    zero4_kernel<<<cdiv(NG / 4, 256), 256>>>((float4*)rdrev, NG / 4);
    zero4_kernel<<<cdiv(ND / 4, 256), 256>>>((float4*)rdd, ND / 4);
    deg_kernel<<<cdiv(EGG, 256), 256>>>(gg_dst, EGG, rdgg);
    deg_kernel<<<cdiv(EGDA, 256), 256>>>(gda_src, EGDA, rdrev);
    deg_kernel<<<cdiv(EGDA, 256), 256>>>(gda_dst, EGDA, rdd);
    rdeg_kernel<<<cdiv(NG, 256), 256>>>(rdgg, NG);
    rdeg_kernel<<<cdiv(NG, 256), 256>>>(rdrev, NG);
    rdeg_kernel<<<cdiv(ND, 256), 256>>>(rdd, ND);

    // ---- combine weights (A_i = Wd_i @ Wu_top_i, B_i = Ws_i @ Wu_bot_i) ----
    const float* Wd[2] = {W_dst1, W_dst2};
    const float* Ws[2] = {W_src1, W_src2};
    const float* Wu[2] = {W_upd1, W_upd2};
    for (int l = 0; l < 2; ++l) {
        // WgX = 0.5*(A0 + A2)
        fgemm_kernel<<<1, 256>>>(Wd[l] + 0 * MM, Wu[l] + 0 * WU, nullptr,
                                 Wd[l] + 2 * MM, Wu[l] + 2 * WU, nullptr,
                                 nullptr, nullptr, nullptr, nullptr, 0.5f, WgX + l * MM, 128);
        // WgA = 0.5*B0
        fgemm_kernel<<<1, 256>>>(Ws[l] + 0 * MM, Wu[l] + 0 * WU + WUB, nullptr,
                                 nullptr, nullptr, nullptr, nullptr, nullptr, nullptr,
                                 nullptr, 0.5f, WgA + l * MM, 128);
        // WgR = 0.5*B2
        fgemm_kernel<<<1, 256>>>(Ws[l] + 2 * MM, Wu[l] + 2 * WU + WUB, nullptr,
                                 nullptr, nullptr, nullptr, nullptr, nullptr, nullptr,
                                 nullptr, 0.5f, WgR + l * MM, 128);
        // WdX = A1
        fgemm_kernel<<<1, 256>>>(Wd[l] + 1 * MM, Wu[l] + 1 * WU, nullptr,
                                 nullptr, nullptr, nullptr, nullptr, nullptr, nullptr,
                                 nullptr, 1.0f, WdX + l * MM, 128);
        // WdA = B1
        fgemm_kernel<<<1, 256>>>(Ws[l] + 1 * MM, Wu[l] + 1 * WU + WUB, nullptr,
                                 nullptr, nullptr, nullptr, nullptr, nullptr, nullptr,
                                 nullptr, 1.0f, WdA + l * MM, 128);
    }
    bias_combine_kernel<<<4, 128>>>(b_dst1, b_src1, b_upd1, W_upd1,
                                    b_dst2, b_src2, b_upd2, W_upd2);

    const int NG4 = NG * HD / 4, ND4 = ND * HD / 4;
    const int GB = cdiv(NG, 128), DB = cdiv(ND, 128);

    // ---- layer 1 aggregation ----
    zero4_kernel<<<cdiv(NG4, 256), 256>>>((float4*)agg_gg, NG4);
    zero4_kernel<<<cdiv(NG4, 256), 256>>>((float4*)agg_rev, NG4);
    zero4_kernel<<<cdiv(ND4, 256), 256>>>((float4*)agg_d, ND4);
    scatter_kernel<<<cdiv(EGG * 32, 256), 256>>>(x_gene, gg_src, gg_dst, EGG, agg_gg);
    scatter_kernel<<<cdiv(EGDA * 32, 256), 256>>>(x_gene, gda_src, gda_dst, EGDA, agg_d);
    scatter_kernel<<<cdiv(EGDA * 32, 256), 256>>>(x_dis, gda_dst, gda_src, EGDA, agg_rev);

    // ---- layer 1 GEMMs ----
    fgemm_kernel<<<GB, 256>>>(x_gene, WgX, nullptr, agg_gg, WgA, rdgg,
                              agg_rev, WgR, rdrev, bg, 1.0f, g1, NG);
    fgemm_kernel<<<DB, 256>>>(x_dis, WdX, nullptr, agg_d, WdA, rdd,
                              nullptr, nullptr, nullptr, bd, 1.0f, d1, ND);

    // ---- BN + leaky relu ----
    zero4_kernel<<<1, 64>>>((float4*)bnsum, 64);
    zero4_kernel<<<1, 64>>>((float4*)bnsumsq, 64);
    bn_stats_kernel<<<GB, 128>>>(g1, NG, bnsum, bnsumsq);
    bn_stats_kernel<<<DB, 128>>>(d1, ND, bnsum + 128, bnsumsq + 128);
    bn_final_kernel<<<2, 128>>>(bn_gamma, bn_beta);
    bn_apply_kernel<<<cdiv(NG * 32, 256), 256>>>(g1, NG, 0);
    bn_apply_kernel<<<cdiv(ND * 32, 256), 256>>>(d1, ND, 1);

    // ---- layer 2 aggregation ----
    zero4_kernel<<<cdiv(NG4, 256), 256>>>((float4*)agg_gg, NG4);
    zero4_kernel<<<cdiv(NG4, 256), 256>>>((float4*)agg_rev, NG4);
    zero4_kernel<<<cdiv(ND4, 256), 256>>>((float4*)agg_d, ND4);
    scatter_kernel<<<cdiv(EGG * 32, 256), 256>>>(g1, gg_src, gg_dst, EGG, agg_gg);
    scatter_kernel<<<cdiv(EGDA * 32, 256), 256>>>(g1, gda_src, gda_dst, EGDA, agg_d);
    scatter_kernel<<<cdiv(EGDA * 32, 256), 256>>>(d1, gda_dst, gda_src, EGDA, agg_rev);

    // ---- layer 2 GEMMs ----
    fgemm_kernel<<<GB, 256>>>(g1, WgX + MM, nullptr, agg_gg, WgA + MM, rdgg,
                              agg_rev, WgR + MM, rdrev, bg + HD, 1.0f, g2, NG);
    fgemm_kernel<<<DB, 256>>>(d1, WdX + MM, nullptr, agg_d, WdA + MM, rdd,
                              nullptr, nullptr, nullptr, bd + HD, 1.0f, d2, ND);

    // ---- decoder ----
    decode_kernel<<<cdiv(ELAB * 32, 256), 256>>>(label_src, label_dst, out);
}

// round 3
// speedup vs baseline: 1.0662x; 1.0662x over previous
#include <cuda_runtime.h>
#include <cuda_bf16.h>
#include <cstdint>
#include <cstddef>

#define NG 50000
#define ND 20000
#define HD 128
#define EGG 800000
#define EGDA 400000
#define ELAB 200000

// ---------------- scratch (static device arrays; no runtime allocation) ----------------
__device__ float d_agg_gg[(size_t)NG * HD];
__device__ float d_agg_rev[(size_t)NG * HD];
__device__ float d_agg_d[(size_t)ND * HD];
__device__ float d_g1[(size_t)NG * HD];
__device__ float d_d1[(size_t)ND * HD];
__device__ float d_g2[(size_t)NG * HD];
__device__ float d_d2[(size_t)ND * HD];
__device__ float d_rdeg_gg[NG];
__device__ float d_rdeg_rev[NG];
__device__ float d_rdeg_d[ND];
// combined weights: per layer [WgX, WgA, WgR, WdX, WdA], each 128x128 ([k][n] row-major)
__device__ float d_Wc[10 * 16384];
// transposed split bf16 weights [n][k]
__device__ __nv_bfloat16 d_Wh[10 * 16384];
__device__ __nv_bfloat16 d_Wl[10 * 16384];
__device__ float d_bg[2][HD];
__device__ float d_bd[2][HD];
__device__ float d_bn_sum[2 * HD];
__device__ float d_bn_sumsq[2 * HD];
__device__ float d_bn_scale[2][HD];
__device__ float d_bn_shift[2][HD];

// ---------------- utility kernels ----------------
__global__ void zero4_kernel(float4* p, int n4) {
    int i = blockIdx.x * blockDim.x + threadIdx.x;
    if (i < n4) p[i] = make_float4(0.f, 0.f, 0.f, 0.f);
}
__global__ void deg_kernel(const int* __restrict__ dst, int nE, float* __restrict__ deg) {
    int i = blockIdx.x * blockDim.x + threadIdx.x;
    if (i < nE) atomicAdd(&deg[dst[i]], 1.0f);
}
__global__ void rdeg_kernel(float* __restrict__ d, int n) {
    int i = blockIdx.x * blockDim.x + threadIdx.x;
    if (i < n) d[i] = 1.0f / fmaxf(d[i], 1.0f);
}
__global__ void scatter_kernel(const float* __restrict__ X, const int* __restrict__ src,
                               const int* __restrict__ dst, int nE, float* __restrict__ agg) {
    int i = blockIdx.x * blockDim.x + threadIdx.x;
    int e = i >> 5;
    int q = i & 31;
    if (e >= nE) return;
    int s = __ldg(&src[e]);
    int d0 = __ldg(&dst[e]);
    float4 v = *(const float4*)&X[(size_t)s * HD + q * 4];
    float* p = &agg[(size_t)d0 * HD + q * 4];
    asm volatile("red.global.add.v4.f32 [%0], {%1, %2, %3, %4};"
                 :: "l"(p), "f"(v.x), "f"(v.y), "f"(v.z), "f"(v.w) : "memory");
}

// ---------------- small fp32 GEMM for weight combine (128x128x128) ----------------
__global__ __launch_bounds__(256) void fgemm_kernel(
    const float* __restrict__ X0, const float* __restrict__ W0,
    const float* __restrict__ X1, const float* __restrict__ W1,
    float post_scale, float* __restrict__ out, int n) {
    __shared__ __align__(16) float Xs[16][132];
    __shared__ __align__(16) float Ws[16][128];
    int tid = threadIdx.x;
    int m0 = blockIdx.x * 128;
    float acc[8][8];
#pragma unroll
    for (int i = 0; i < 8; ++i)
#pragma unroll
        for (int j = 0; j < 8; ++j) acc[i][j] = 0.f;
    const float* Xp[2] = {X0, X1};
    const float* Wp[2] = {W0, W1};
    int rA = tid >> 2, kq = tid & 3, krow = tid >> 4, cq = tid & 15;
    int tx = tid & 15, ty = tid >> 4;
    for (int t = 0; t < 2; ++t) {
        const float* X = Xp[t];
        if (!X) continue;
        const float* W = Wp[t];
        for (int kc = 0; kc < 8; ++kc) {
#pragma unroll
            for (int h = 0; h < 2; ++h) {
                int r = rA + h * 64;
                int gm = m0 + r;
                float4 v = make_float4(0.f, 0.f, 0.f, 0.f);
                if (gm < n) v = *(const float4*)&X[(size_t)gm * 128 + kc * 16 + kq * 4];
                Xs[kq * 4 + 0][r] = v.x;
                Xs[kq * 4 + 1][r] = v.y;
                Xs[kq * 4 + 2][r] = v.z;
                Xs[kq * 4 + 3][r] = v.w;
            }
#pragma unroll
            for (int h = 0; h < 2; ++h) {
                int c = cq + h * 16;
                *(float4*)&Ws[krow][c * 4] = *(const float4*)&W[(size_t)(kc * 16 + krow) * 128 + c * 4];
            }
            __syncthreads();
#pragma unroll
            for (int k = 0; k < 16; ++k) {
                float a[8], b[8];
                *(float4*)&a[0] = *(const float4*)&Xs[k][ty * 8];
                *(float4*)&a[4] = *(const float4*)&Xs[k][ty * 8 + 4];
                *(float4*)&b[0] = *(const float4*)&Ws[k][tx * 8];
                *(float4*)&b[4] = *(const float4*)&Ws[k][tx * 8 + 4];
#pragma unroll
                for (int i = 0; i < 8; ++i)
#pragma unroll
                    for (int j = 0; j < 8; ++j) acc[i][j] = fmaf(a[i], b[j], acc[i][j]);
            }
            __syncthreads();
        }
    }
#pragma unroll
    for (int i = 0; i < 8; ++i) {
        int gm = m0 + ty * 8 + i;
        if (gm >= n) continue;
#pragma unroll
        for (int j = 0; j < 8; ++j) out[(size_t)gm * 128 + tx * 8 + j] = acc[i][j] * post_scale;
    }
}

// transpose + bf16 hi/lo split: in [k][n] fp32 -> out [n][k] bf16 pair
__global__ void wsplit_kernel(const float* __restrict__ Wc, __nv_bfloat16* __restrict__ Wh,
                              __nv_bfloat16* __restrict__ Wl) {
    int mat = blockIdx.x;
    const float* in = Wc + (size_t)mat * 16384;
    __nv_bfloat16* oh = Wh + (size_t)mat * 16384;
    __nv_bfloat16* ol = Wl + (size_t)mat * 16384;
    for (int i = threadIdx.x; i < 16384; i += blockDim.x) {
        int nn = i >> 7, kk = i & 127;
        float v = in[kk * 128 + nn];
        __nv_bfloat16 h = __float2bfloat16(v);
        oh[i] = h;
        ol[i] = __float2bfloat16(v - __bfloat162float(h));
    }
}

// ---------------- mma.sync node GEMM (bf16 hi/lo split, fp32 accum) ----------------
// out[m][:] = sum_t ((r_t? r_t[m]:1) * X_t[m][:]) @ W_t + bias ; W_t given as [n][k] bf16 hi/lo
#define LDA 136  // padded bf16 stride (272B: 16B-aligned, conflict-free fragment loads)
#define SM_MAT (128 * LDA)
#define SMEM_TOTAL (4 * SM_MAT * 2)

__device__ __forceinline__ void mma_bf16(float* c, const uint32_t* a, const uint32_t* b) {
    asm volatile(
        "mma.sync.aligned.m16n8k16.row.col.f32.bf16.bf16.f32 "
        "{%0,%1,%2,%3}, {%4,%5,%6,%7}, {%8,%9}, {%0,%1,%2,%3};"
        : "+f"(c[0]), "+f"(c[1]), "+f"(c[2]), "+f"(c[3])
        : "r"(a[0]), "r"(a[1]), "r"(a[2]), "r"(a[3]), "r"(b[0]), "r"(b[1]));
}

__global__ __launch_bounds__(256, 1) void mmagemm_kernel(
    const float* __restrict__ X0, const float* __restrict__ r0,
    const __nv_bfloat16* __restrict__ Bh0, const __nv_bfloat16* __restrict__ Bl0,
    const float* __restrict__ X1, const float* __restrict__ r1,
    const __nv_bfloat16* __restrict__ Bh1, const __nv_bfloat16* __restrict__ Bl1,
    const float* __restrict__ X2, const float* __restrict__ r2,
    const __nv_bfloat16* __restrict__ Bh2, const __nv_bfloat16* __restrict__ Bl2,
    const float* __restrict__ bias, float* __restrict__ out, int n, int nterms) {
    extern __shared__ __nv_bfloat16 smem[];
    __nv_bfloat16* Ah = smem;
    __nv_bfloat16* Al = smem + SM_MAT;
    __nv_bfloat16* Bh = smem + 2 * SM_MAT;
    __nv_bfloat16* Bl = smem + 3 * SM_MAT;

    int tid = threadIdx.x;
    int wid = tid >> 5;
    int lane = tid & 31;
    int m0 = blockIdx.x * 128;

    const float* Xa[3] = {X0, X1, X2};
    const float* Ra[3] = {r0, r1, r2};
    const __nv_bfloat16* Bha[3] = {Bh0, Bh1, Bh2};
    const __nv_bfloat16* Bla[3] = {Bl0, Bl1, Bl2};

    // A conversion mapping: each thread does one row-half (64 k)
    int arow = tid >> 1;
    int akh = (tid & 1) * 64;
    int gma = m0 + arow;
    bool avalid = gma < n;

    // warp tile: 32 rows x 64 cols
    int wr = (wid & 3) * 32;
    int wc = (wid >> 2) * 64;
    int g = lane >> 2;   // group id 0..7
    int tg = lane & 3;   // thread in group

    float acc[2][8][4];
#pragma unroll
    for (int mt = 0; mt < 2; ++mt)
#pragma unroll
        for (int nt = 0; nt < 8; ++nt)
#pragma unroll
            for (int q = 0; q < 4; ++q) acc[mt][nt][q] = 0.f;

    for (int t = 0; t < nterms; ++t) {
        __syncthreads();  // previous term's fragment reads done
        // ---- A tile: fp32 -> bf16 hi/lo, row-scaled ----
        {
            const float* X = Xa[t];
            const float* R = Ra[t];
            float sc = 0.f;
            if (avalid) sc = R ? __ldg(&R[gma]) : 1.0f;
            const float* xrow = X + (size_t)gma * 128 + akh;
            int base = arow * LDA + akh;
#pragma unroll
            for (int c = 0; c < 8; ++c) {
                float4 v0 = make_float4(0.f, 0.f, 0.f, 0.f), v1 = v0;
                if (avalid) {
                    v0 = *(const float4*)(xrow + c * 8);
                    v1 = *(const float4*)(xrow + c * 8 + 4);
                    v0.x *= sc; v0.y *= sc; v0.z *= sc; v0.w *= sc;
                    v1.x *= sc; v1.y *= sc; v1.z *= sc; v1.w *= sc;
                }
                __nv_bfloat162 h0 = __floats2bfloat162_rn(v0.x, v0.y);
                __nv_bfloat162 h1 = __floats2bfloat162_rn(v0.z, v0.w);
                __nv_bfloat162 h2 = __floats2bfloat162_rn(v1.x, v1.y);
                __nv_bfloat162 h3 = __floats2bfloat162_rn(v1.z, v1.w);
                float2 f0 = __bfloat1622float2(h0), f1 = __bfloat1622float2(h1);
                float2 f2 = __bfloat1622float2(h2), f3 = __bfloat1622float2(h3);
                __nv_bfloat162 l0 = __floats2bfloat162_rn(v0.x - f0.x, v0.y - f0.y);
                __nv_bfloat162 l1 = __floats2bfloat162_rn(v0.z - f1.x, v0.w - f1.y);
                __nv_bfloat162 l2 = __floats2bfloat162_rn(v1.x - f2.x, v1.y - f2.y);
                __nv_bfloat162 l3 = __floats2bfloat162_rn(v1.z - f3.x, v1.w - f3.y);
                uint4 hv, lv;
                hv.x = *(uint32_t*)&h0; hv.y = *(uint32_t*)&h1;
                hv.z = *(uint32_t*)&h2; hv.w = *(uint32_t*)&h3;
                lv.x = *(uint32_t*)&l0; lv.y = *(uint32_t*)&l1;
                lv.z = *(uint32_t*)&l2; lv.w = *(uint32_t*)&l3;
                *(uint4*)&Ah[base + c * 8] = hv;
                *(uint4*)&Al[base + c * 8] = lv;
            }
        }
        // ---- B tile copy ([n][k] bf16 -> padded smem) ----
        {
            const __nv_bfloat16* bh = Bha[t];
            const __nv_bfloat16* bl = Bla[t];
#pragma unroll
            for (int c = 0; c < 8; ++c) {
                int chunk = c * 256 + tid;  // 2048 chunks of 8 bf16
                int row = chunk >> 4;
                int k0 = (chunk & 15) * 8;
                int d = row * LDA + k0;
                *(uint4*)&Bh[d] = *(const uint4*)(bh + (size_t)chunk * 8);
                *(uint4*)&Bl[d] = *(const uint4*)(bl + (size_t)chunk * 8);
            }
        }
        __syncthreads();
        // ---- mma accumulation over K ----
#pragma unroll
        for (int ks = 0; ks < 8; ++ks) {
            int kb = ks * 16;
            uint32_t ah[2][4], al[2][4], bhf[8][2], blf[8][2];
#pragma unroll
            for (int mt = 0; mt < 2; ++mt) {
                int r = wr + mt * 16 + g;
                int o0 = r * LDA + kb + tg * 2;
                int o1 = (r + 8) * LDA + kb + tg * 2;
                ah[mt][0] = *(uint32_t*)&Ah[o0];
                ah[mt][1] = *(uint32_t*)&Ah[o1];
                ah[mt][2] = *(uint32_t*)&Ah[o0 + 8];
                ah[mt][3] = *(uint32_t*)&Ah[o1 + 8];
                al[mt][0] = *(uint32_t*)&Al[o0];
                al[mt][1] = *(uint32_t*)&Al[o1];
                al[mt][2] = *(uint32_t*)&Al[o0 + 8];
                al[mt][3] = *(uint32_t*)&Al[o1 + 8];
            }
#pragma unroll
            for (int nt = 0; nt < 8; ++nt) {
                int c = wc + nt * 8 + g;
                int o = c * LDA + kb + tg * 2;
                bhf[nt][0] = *(uint32_t*)&Bh[o];
                bhf[nt][1] = *(uint32_t*)&Bh[o + 8];
                blf[nt][0] = *(uint32_t*)&Bl[o];
                blf[nt][1] = *(uint32_t*)&Bl[o + 8];
            }
#pragma unroll
            for (int mt = 0; mt < 2; ++mt)
#pragma unroll
                for (int nt = 0; nt < 8; ++nt) {
                    mma_bf16(acc[mt][nt], ah[mt], bhf[nt]);
                    mma_bf16(acc[mt][nt], ah[mt], blf[nt]);
                    mma_bf16(acc[mt][nt], al[mt], bhf[nt]);
                }
        }
    }

    // ---- epilogue: c0,c1 at (row, col..col+1), c2,c3 at (row+8, ...) ----
#pragma unroll
    for (int mt = 0; mt < 2; ++mt) {
        int r0v = m0 + wr + mt * 16 + g;
        int r1v = r0v + 8;
#pragma unroll
        for (int nt = 0; nt < 8; ++nt) {
            int col = wc + nt * 8 + tg * 2;
            float b0 = __ldg(&bias[col]);
            float b1 = __ldg(&bias[col + 1]);
            if (r0v < n) {
                float2 o = make_float2(acc[mt][nt][0] + b0, acc[mt][nt][1] + b1);
                *(float2*)&out[(size_t)r0v * 128 + col] = o;
            }
            if (r1v < n) {
                float2 o = make_float2(acc[mt][nt][2] + b0, acc[mt][nt][3] + b1);
                *(float2*)&out[(size_t)r1v * 128 + col] = o;
            }
        }
    }
}

// ---------------- bias combine ----------------
__global__ void bias_combine_kernel(const float* __restrict__ bd1, const float* __restrict__ bs1,
                                    const float* __restrict__ bu1, const float* __restrict__ Wu1,
                                    const float* __restrict__ bd2, const float* __restrict__ bs2,
                                    const float* __restrict__ bu2, const float* __restrict__ Wu2) {
    int layer = blockIdx.x >> 1;
    int which = blockIdx.x & 1;
    int h = threadIdx.x;
    const float* bd = layer ? bd2 : bd1;
    const float* bs = layer ? bs2 : bs1;
    const float* bu = layer ? bu2 : bu1;
    const float* Wu = layer ? Wu2 : Wu1;
    auto cfun = [&](int i) {
        float s = bu[i * 128 + h];
        const float* wt = Wu + (size_t)i * 32768;
        for (int k = 0; k < 128; ++k) s = fmaf(bd[i * 128 + k], wt[k * 128 + h], s);
        const float* wb = wt + 16384;
        for (int k = 0; k < 128; ++k) s = fmaf(bs[i * 128 + k], wb[k * 128 + h], s);
        return s;
    };
    if (which == 0)
        d_bg[layer][h] = 0.5f * (cfun(0) + cfun(2));
    else
        d_bd[layer][h] = cfun(1);
}

// ---------------- batch norm ----------------
__global__ void bn_stats_kernel(const float* __restrict__ x, int n,
                                float* __restrict__ sum, float* __restrict__ sumsq) {
    int c = threadIdx.x;
    int r0 = blockIdx.x * 128;
    int rend = min(r0 + 128, n);
    float s = 0.f, s2 = 0.f;
    for (int r = r0; r < rend; ++r) {
        float v = x[(size_t)r * 128 + c];
        s += v;
        s2 = fmaf(v, v, s2);
    }
    atomicAdd(&sum[c], s);
    atomicAdd(&sumsq[c], s2);
}
__global__ void bn_final_kernel(const float* __restrict__ gamma, const float* __restrict__ beta) {
    int idx = blockIdx.x;
    int c = threadIdx.x;
    float nn = (idx == 0) ? (float)NG : (float)ND;
    float mean = d_bn_sum[idx * 128 + c] / nn;
    float var = d_bn_sumsq[idx * 128 + c] / nn - mean * mean;
    float sc = gamma[idx * 128 + c] * rsqrtf(var + 1e-5f);
    d_bn_scale[idx][c] = sc;
    d_bn_shift[idx][c] = beta[idx * 128 + c] - mean * sc;
}
__global__ void bn_apply_kernel(float* __restrict__ x, int n, int which) {
    int i = blockIdx.x * blockDim.x + threadIdx.x;
    if (i >= n * 32) return;
    int q = i & 31;
    int c = q * 4;
    const float* sc = d_bn_scale[which];
    const float* sh = d_bn_shift[which];
    float4 v = *(float4*)&x[(size_t)i * 4];
    v.x = fmaf(v.x, sc[c + 0], sh[c + 0]);
    v.y = fmaf(v.y, sc[c + 1], sh[c + 1]);
    v.z = fmaf(v.z, sc[c + 2], sh[c + 2]);
    v.w = fmaf(v.w, sc[c + 3], sh[c + 3]);
    v.x = v.x >= 0.f ? v.x : 0.01f * v.x;
    v.y = v.y >= 0.f ? v.y : 0.01f * v.y;
    v.z = v.z >= 0.f ? v.z : 0.01f * v.z;
    v.w = v.w >= 0.f ? v.w : 0.01f * v.w;
    *(float4*)&x[(size_t)i * 4] = v;
}

// ---------------- decoder ----------------
__global__ void decode_kernel(const int* __restrict__ ls, const int* __restrict__ ld,
                              float* __restrict__ out) {
    int gw = (blockIdx.x * blockDim.x + threadIdx.x) >> 5;
    int lane = threadIdx.x & 31;
    if (gw >= ELAB) return;
    int a = __ldg(&ls[gw]);
    int b = __ldg(&ld[gw]);
    float4 u = *(const float4*)&d_g2[(size_t)a * 128 + lane * 4];
    float4 v = *(const float4*)&d_d2[(size_t)b * 128 + lane * 4];
    float s = u.x * v.x + u.y * v.y + u.z * v.z + u.w * v.w;
#pragma unroll
    for (int o = 16; o; o >>= 1) s += __shfl_xor_sync(0xFFFFFFFFu, s, o);
    if (lane == 0) out[gw] = s;
}

// ---------------- launch ----------------
static inline int cdiv(int a, int b) { return (a + b - 1) / b; }

extern "C" void kernel_launch(void* const* d_in, const int* in_sizes, int n_in,
                              void* d_out, int out_size) {
    const float* x_gene = (const float*)d_in[0];
    const float* x_dis  = (const float*)d_in[1];
    const float* W_dst1 = (const float*)d_in[2];
    const float* W_src1 = (const float*)d_in[3];
    const float* W_upd1 = (const float*)d_in[4];
    const float* b_dst1 = (const float*)d_in[5];
    const float* b_src1 = (const float*)d_in[6];
    const float* b_upd1 = (const float*)d_in[7];
    const float* W_dst2 = (const float*)d_in[8];
    const float* W_src2 = (const float*)d_in[9];
    const float* W_upd2 = (const float*)d_in[10];
    const float* b_dst2 = (const float*)d_in[11];
    const float* b_src2 = (const float*)d_in[12];
    const float* b_upd2 = (const float*)d_in[13];
    const float* bn_gamma = (const float*)d_in[14];
    const float* bn_beta  = (const float*)d_in[15];
    const int* gg_src  = (const int*)d_in[16];
    const int* gg_dst  = (const int*)d_in[17];
    const int* gda_src = (const int*)d_in[18];
    const int* gda_dst = (const int*)d_in[19];
    const int* label_src = (const int*)d_in[20];
    const int* label_dst = (const int*)d_in[21];
    float* out = (float*)d_out;

    static bool attr_set = false;
    if (!attr_set) {
        cudaFuncSetAttribute(mmagemm_kernel, cudaFuncAttributeMaxDynamicSharedMemorySize, SMEM_TOTAL);
        attr_set = true;
    }

    float *agg_gg, *agg_rev, *agg_d, *g1, *d1, *g2, *d2, *rdgg, *rdrev, *rdd;
    float *Wc, *bg, *bd, *bnsum, *bnsumsq;
    __nv_bfloat16 *Wh, *Wl;
    cudaGetSymbolAddress((void**)&agg_gg, d_agg_gg);
    cudaGetSymbolAddress((void**)&agg_rev, d_agg_rev);
    cudaGetSymbolAddress((void**)&agg_d, d_agg_d);
    cudaGetSymbolAddress((void**)&g1, d_g1);
    cudaGetSymbolAddress((void**)&d1, d_d1);
    cudaGetSymbolAddress((void**)&g2, d_g2);
    cudaGetSymbolAddress((void**)&d2, d_d2);
    cudaGetSymbolAddress((void**)&rdgg, d_rdeg_gg);
    cudaGetSymbolAddress((void**)&rdrev, d_rdeg_rev);
    cudaGetSymbolAddress((void**)&rdd, d_rdeg_d);
    cudaGetSymbolAddress((void**)&Wc, d_Wc);
    cudaGetSymbolAddress((void**)&Wh, d_Wh);
    cudaGetSymbolAddress((void**)&Wl, d_Wl);
    cudaGetSymbolAddress((void**)&bg, d_bg);
    cudaGetSymbolAddress((void**)&bd, d_bd);
    cudaGetSymbolAddress((void**)&bnsum, d_bn_sum);
    cudaGetSymbolAddress((void**)&bnsumsq, d_bn_sumsq);

    const int MM = 16384;
    const int WU = 32768;
    const int WUB = 16384;

    // ---- degrees ----
    zero4_kernel<<<cdiv(NG / 4, 256), 256>>>((float4*)rdgg, NG / 4);
    zero4_kernel<<<cdiv(NG / 4, 256), 256>>>((float4*)rdrev, NG / 4);
    zero4_kernel<<<cdiv(ND / 4, 256), 256>>>((float4*)rdd, ND / 4);
    deg_kernel<<<cdiv(EGG, 256), 256>>>(gg_dst, EGG, rdgg);
    deg_kernel<<<cdiv(EGDA, 256), 256>>>(gda_src, EGDA, rdrev);
    deg_kernel<<<cdiv(EGDA, 256), 256>>>(gda_dst, EGDA, rdd);
    rdeg_kernel<<<cdiv(NG, 256), 256>>>(rdgg, NG);
    rdeg_kernel<<<cdiv(NG, 256), 256>>>(rdrev, NG);
    rdeg_kernel<<<cdiv(ND, 256), 256>>>(rdd, ND);

    // ---- combine weights into d_Wc: [WgX, WgA, WgR, WdX, WdA] per layer ----
    const float* Wd[2] = {W_dst1, W_dst2};
    const float* Ws[2] = {W_src1, W_src2};
    const float* Wu[2] = {W_upd1, W_upd2};
    for (int l = 0; l < 2; ++l) {
        float* base = Wc + (size_t)l * 5 * MM;
        fgemm_kernel<<<1, 256>>>(Wd[l] + 0 * MM, Wu[l] + 0 * WU,
                                 Wd[l] + 2 * MM, Wu[l] + 2 * WU, 0.5f, base + 0 * MM, 128);
        fgemm_kernel<<<1, 256>>>(Ws[l] + 0 * MM, Wu[l] + 0 * WU + WUB,
                                 nullptr, nullptr, 0.5f, base + 1 * MM, 128);
        fgemm_kernel<<<1, 256>>>(Ws[l] + 2 * MM, Wu[l] + 2 * WU + WUB,
                                 nullptr, nullptr, 0.5f, base + 2 * MM, 128);
        fgemm_kernel<<<1, 256>>>(Wd[l] + 1 * MM, Wu[l] + 1 * WU,
                                 nullptr, nullptr, 1.0f, base + 3 * MM, 128);
        fgemm_kernel<<<1, 256>>>(Ws[l] + 1 * MM, Wu[l] + 1 * WU + WUB,
                                 nullptr, nullptr, 1.0f, base + 4 * MM, 128);
    }
    wsplit_kernel<<<10, 256>>>(Wc, Wh, Wl);
    bias_combine_kernel<<<4, 128>>>(b_dst1, b_src1, b_upd1, W_upd1,
                                    b_dst2, b_src2, b_upd2, W_upd2);

    const int NG4 = NG * HD / 4, ND4 = ND * HD / 4;
    const int GB = cdiv(NG, 128), DB = cdiv(ND, 128);
    auto WH = [&](int l, int j) { return Wh + (size_t)(l * 5 + j) * MM; };
    auto WL = [&](int l, int j) { return Wl + (size_t)(l * 5 + j) * MM; };

    // ---- layer 1 aggregation ----
    zero4_kernel<<<cdiv(NG4, 256), 256>>>((float4*)agg_gg, NG4);
    zero4_kernel<<<cdiv(NG4, 256), 256>>>((float4*)agg_rev, NG4);
    zero4_kernel<<<cdiv(ND4, 256), 256>>>((float4*)agg_d, ND4);
    scatter_kernel<<<cdiv(EGG * 32, 256), 256>>>(x_gene, gg_src, gg_dst, EGG, agg_gg);
    scatter_kernel<<<cdiv(EGDA * 32, 256), 256>>>(x_gene, gda_src, gda_dst, EGDA, agg_d);
    scatter_kernel<<<cdiv(EGDA * 32, 256), 256>>>(x_dis, gda_dst, gda_src, EGDA, agg_rev);

    // ---- layer 1 GEMMs (tensor cores via mma.sync) ----
    mmagemm_kernel<<<GB, 256, SMEM_TOTAL>>>(
        x_gene, nullptr, WH(0, 0), WL(0, 0),
        agg_gg, rdgg, WH(0, 1), WL(0, 1),
        agg_rev, rdrev, WH(0, 2), WL(0, 2),
        bg, g1, NG, 3);
    mmagemm_kernel<<<DB, 256, SMEM_TOTAL>>>(
        x_dis, nullptr, WH(0, 3), WL(0, 3),
        agg_d, rdd, WH(0, 4), WL(0, 4),
        nullptr, nullptr, nullptr, nullptr,
        bd, d1, ND, 2);

    // ---- BN + leaky relu ----
    zero4_kernel<<<1, 64>>>((float4*)bnsum, 64);
    zero4_kernel<<<1, 64>>>((float4*)bnsumsq, 64);
    bn_stats_kernel<<<GB, 128>>>(g1, NG, bnsum, bnsumsq);
    bn_stats_kernel<<<DB, 128>>>(d1, ND, bnsum + 128, bnsumsq + 128);
    bn_final_kernel<<<2, 128>>>(bn_gamma, bn_beta);
    bn_apply_kernel<<<cdiv(NG * 32, 256), 256>>>(g1, NG, 0);
    bn_apply_kernel<<<cdiv(ND * 32, 256), 256>>>(d1, ND, 1);

    // ---- layer 2 aggregation ----
    zero4_kernel<<<cdiv(NG4, 256), 256>>>((float4*)agg_gg, NG4);
    zero4_kernel<<<cdiv(NG4, 256), 256>>>((float4*)agg_rev, NG4);
    zero4_kernel<<<cdiv(ND4, 256), 256>>>((float4*)agg_d, ND4);
    scatter_kernel<<<cdiv(EGG * 32, 256), 256>>>(g1, gg_src, gg_dst, EGG, agg_gg);
    scatter_kernel<<<cdiv(EGDA * 32, 256), 256>>>(g1, gda_src, gda_dst, EGDA, agg_d);
    scatter_kernel<<<cdiv(EGDA * 32, 256), 256>>>(d1, gda_dst, gda_src, EGDA, agg_rev);

    // ---- layer 2 GEMMs ----
    mmagemm_kernel<<<GB, 256, SMEM_TOTAL>>>(
        g1, nullptr, WH(1, 0), WL(1, 0),
        agg_gg, rdgg, WH(1, 1), WL(1, 1),
        agg_rev, rdrev, WH(1, 2), WL(1, 2),
        bg + HD, g2, NG, 3);
    mmagemm_kernel<<<DB, 256, SMEM_TOTAL>>>(
        d1, nullptr, WH(1, 3), WL(1, 3),
        agg_d, rdd, WH(1, 4), WL(1, 4),
        nullptr, nullptr, nullptr, nullptr,
        bd + HD, d2, ND, 2);

    // ---- decoder ----
    decode_kernel<<<cdiv(ELAB * 32, 256), 256>>>(label_src, label_dst, out);
}

// round 5
// speedup vs baseline: 1.2564x; 1.1784x over previous
#include <cuda_runtime.h>
#include <cuda_bf16.h>
#include <cstdint>
#include <cstddef>

#define NG 50000
#define ND 20000
#define HD 128
#define EGG 800000
#define EGDA 400000
#define ELAB 200000
#define ETOT (EGG + 2 * EGDA)

// ---------------- scratch (static device arrays; no runtime allocation) ----------------
__device__ float d_agg_gg[(size_t)NG * HD];
__device__ float d_agg_rev[(size_t)NG * HD];
__device__ float d_agg_d[(size_t)ND * HD];
__device__ float d_g1[(size_t)NG * HD];
__device__ float d_d1[(size_t)ND * HD];
__device__ float d_g2[(size_t)NG * HD];
__device__ float d_d2[(size_t)ND * HD];
__device__ float d_rdeg_gg[NG];
__device__ float d_rdeg_rev[NG];
__device__ float d_rdeg_d[ND];
// CSR structures (built once, reused by both layers)
__device__ int d_ideg[NG + ND + NG];   // [gg | d | rev]
__device__ int d_ptr_gg[NG + 1];
__device__ int d_ptr_d[ND + 1];
__device__ int d_ptr_rev[NG + 1];
__device__ int d_cur_gg[NG];
__device__ int d_cur_d[ND];
__device__ int d_cur_rev[NG];
__device__ int d_idx_gg[EGG];
__device__ int d_idx_d[EGDA];
__device__ int d_idx_rev[EGDA];
// combined weights: per layer [WgX, WgA, WgR, WdX, WdA], each 128x128 ([k][n] row-major)
__device__ float d_Wc[10 * 16384];
__device__ __nv_bfloat16 d_Wh[10 * 16384];
__device__ __nv_bfloat16 d_Wl[10 * 16384];
__device__ float d_bg[2][HD];
__device__ float d_bd[2][HD];
__device__ float d_bn_sum[2 * HD];
__device__ float d_bn_sumsq[2 * HD];
__device__ float d_bn_scale[2][HD];
__device__ float d_bn_shift[2][HD];

// ---------------- CSR build kernels ----------------
__global__ void zero_int_kernel(int* p, int n) {
    int i = blockIdx.x * blockDim.x + threadIdx.x;
    if (i < n) p[i] = 0;
}

// count degrees for all 3 relations in one pass
__global__ void deg_all_kernel(const int* __restrict__ gg_dst, const int* __restrict__ gda_dst,
                               const int* __restrict__ gda_src, int* __restrict__ ideg) {
    int i = blockIdx.x * blockDim.x + threadIdx.x;
    if (i < EGG) {
        atomicAdd(&ideg[__ldg(&gg_dst[i])], 1);
    } else if (i < EGG + EGDA) {
        atomicAdd(&ideg[NG + __ldg(&gda_dst[i - EGG])], 1);
    } else if (i < ETOT) {
        atomicAdd(&ideg[NG + ND + __ldg(&gda_src[i - EGG - EGDA])], 1);
    }
}

// chunked exclusive scan, one block (1024 threads) per relation
__global__ void scan_all_kernel() {
    __shared__ int sm[1024];
    int rel = blockIdx.x;
    const int* deg;
    int n;
    int* ptr;
    int* cur;
    if (rel == 0) { deg = d_ideg; n = NG; ptr = d_ptr_gg; cur = d_cur_gg; }
    else if (rel == 1) { deg = d_ideg + NG; n = ND; ptr = d_ptr_d; cur = d_cur_d; }
    else { deg = d_ideg + NG + ND; n = NG; ptr = d_ptr_rev; cur = d_cur_rev; }
    int tid = threadIdx.x;
    int chunk = (n + 1023) >> 10;
    int lo = tid * chunk;
    int hi = min(lo + chunk, n);
    int s = 0;
    for (int i = lo; i < hi; ++i) s += deg[i];
    sm[tid] = s;
    __syncthreads();
    for (int off = 1; off < 1024; off <<= 1) {
        int v = 0;
        if (tid >= off) v = sm[tid - off];
        __syncthreads();
        sm[tid] += v;
        __syncthreads();
    }
    int run = sm[tid] - s;  // exclusive prefix for this chunk
    for (int i = lo; i < hi; ++i) {
        ptr[i] = run;
        cur[i] = run;
        run += deg[i];
    }
    if (tid == 1023) ptr[n] = sm[1023];
}

__global__ void fill_all_kernel(const int* __restrict__ gg_src, const int* __restrict__ gg_dst,
                                const int* __restrict__ gda_src, const int* __restrict__ gda_dst) {
    int i = blockIdx.x * blockDim.x + threadIdx.x;
    if (i < EGG) {
        int p = atomicAdd(&d_cur_gg[__ldg(&gg_dst[i])], 1);
        d_idx_gg[p] = __ldg(&gg_src[i]);
    } else if (i < EGG + EGDA) {
        int e = i - EGG;
        int p = atomicAdd(&d_cur_d[__ldg(&gda_dst[e])], 1);
        d_idx_d[p] = __ldg(&gda_src[e]);
    } else if (i < ETOT) {
        int e = i - EGG - EGDA;
        int p = atomicAdd(&d_cur_rev[__ldg(&gda_src[e])], 1);
        d_idx_rev[p] = __ldg(&gda_dst[e]);
    }
}

__global__ void rdeg_all_kernel() {
    int i = blockIdx.x * blockDim.x + threadIdx.x;
    if (i < NG) d_rdeg_gg[i] = 1.0f / fmaxf((float)d_ideg[i], 1.0f);
    else if (i < NG + ND) d_rdeg_d[i - NG] = 1.0f / fmaxf((float)d_ideg[i], 1.0f);
    else if (i < NG + ND + NG) d_rdeg_rev[i - NG - ND] = 1.0f / fmaxf((float)d_ideg[i], 1.0f);
}

// ---------------- gather aggregation (warp per dst row, mean folded in) ----------------
__global__ __launch_bounds__(256) void gather_kernel(
    const float* __restrict__ X, const int* __restrict__ ptr, const int* __restrict__ idx,
    const float* __restrict__ rdeg, float* __restrict__ out, int n) {
    int w = (blockIdx.x * blockDim.x + threadIdx.x) >> 5;
    int lane = threadIdx.x & 31;
    if (w >= n) return;
    int s = __ldg(&ptr[w]);
    int e = __ldg(&ptr[w + 1]);
    float4 a0 = make_float4(0.f, 0.f, 0.f, 0.f);
    float4 a1 = make_float4(0.f, 0.f, 0.f, 0.f);
    int j = s;
    for (; j + 1 < e; j += 2) {
        int n0 = __ldg(&idx[j]);
        int n1 = __ldg(&idx[j + 1]);
        float4 v0 = *(const float4*)&X[(size_t)n0 * HD + lane * 4];
        float4 v1 = *(const float4*)&X[(size_t)n1 * HD + lane * 4];
        a0.x += v0.x; a0.y += v0.y; a0.z += v0.z; a0.w += v0.w;
        a1.x += v1.x; a1.y += v1.y; a1.z += v1.z; a1.w += v1.w;
    }
    if (j < e) {
        int n0 = __ldg(&idx[j]);
        float4 v0 = *(const float4*)&X[(size_t)n0 * HD + lane * 4];
        a0.x += v0.x; a0.y += v0.y; a0.z += v0.z; a0.w += v0.w;
    }
    float r = __ldg(&rdeg[w]);
    float4 o;
    o.x = (a0.x + a1.x) * r;
    o.y = (a0.y + a1.y) * r;
    o.z = (a0.z + a1.z) * r;
    o.w = (a0.w + a1.w) * r;
    *(float4*)&out[(size_t)w * HD + lane * 4] = o;
}

// ---------------- small fp32 GEMM for weight combine (128x128x128) ----------------
__global__ __launch_bounds__(256) void fgemm_kernel(
    const float* __restrict__ X0, const float* __restrict__ W0,
    const float* __restrict__ X1, const float* __restrict__ W1,
    float post_scale, float* __restrict__ out, int n) {
    __shared__ __align__(16) float Xs[16][132];
    __shared__ __align__(16) float Ws[16][128];
    int tid = threadIdx.x;
    int m0 = blockIdx.x * 128;
    float acc[8][8];
#pragma unroll
    for (int i = 0; i < 8; ++i)
#pragma unroll
        for (int j = 0; j < 8; ++j) acc[i][j] = 0.f;
    const float* Xp[2] = {X0, X1};
    const float* Wp[2] = {W0, W1};
    int rA = tid >> 2, kq = tid & 3, krow = tid >> 4, cq = tid & 15;
    int tx = tid & 15, ty = tid >> 4;
    for (int t = 0; t < 2; ++t) {
        const float* X = Xp[t];
        if (!X) continue;
        const float* W = Wp[t];
        for (int kc = 0; kc < 8; ++kc) {
#pragma unroll
            for (int h = 0; h < 2; ++h) {
                int r = rA + h * 64;
                int gm = m0 + r;
                float4 v = make_float4(0.f, 0.f, 0.f, 0.f);
                if (gm < n) v = *(const float4*)&X[(size_t)gm * 128 + kc * 16 + kq * 4];
                Xs[kq * 4 + 0][r] = v.x;
                Xs[kq * 4 + 1][r] = v.y;
                Xs[kq * 4 + 2][r] = v.z;
                Xs[kq * 4 + 3][r] = v.w;
            }
#pragma unroll
            for (int h = 0; h < 2; ++h) {
                int c = cq + h * 16;
                *(float4*)&Ws[krow][c * 4] = *(const float4*)&W[(size_t)(kc * 16 + krow) * 128 + c * 4];
            }
            __syncthreads();
#pragma unroll
            for (int k = 0; k < 16; ++k) {
                float a[8], b[8];
                *(float4*)&a[0] = *(const float4*)&Xs[k][ty * 8];
                *(float4*)&a[4] = *(const float4*)&Xs[k][ty * 8 + 4];
                *(float4*)&b[0] = *(const float4*)&Ws[k][tx * 8];
                *(float4*)&b[4] = *(const float4*)&Ws[k][tx * 8 + 4];
#pragma unroll
                for (int i = 0; i < 8; ++i)
#pragma unroll
                    for (int j = 0; j < 8; ++j) acc[i][j] = fmaf(a[i], b[j], acc[i][j]);
            }
            __syncthreads();
        }
    }
#pragma unroll
    for (int i = 0; i < 8; ++i) {
        int gm = m0 + ty * 8 + i;
        if (gm >= n) continue;
#pragma unroll
        for (int j = 0; j < 8; ++j) out[(size_t)gm * 128 + tx * 8 + j] = acc[i][j] * post_scale;
    }
}

// transpose + bf16 hi/lo split: in [k][n] fp32 -> out [n][k] bf16 pair
__global__ void wsplit_kernel(const float* __restrict__ Wc, __nv_bfloat16* __restrict__ Wh,
                              __nv_bfloat16* __restrict__ Wl) {
    int mat = blockIdx.x;
    const float* in = Wc + (size_t)mat * 16384;
    __nv_bfloat16* oh = Wh + (size_t)mat * 16384;
    __nv_bfloat16* ol = Wl + (size_t)mat * 16384;
    for (int i = threadIdx.x; i < 16384; i += blockDim.x) {
        int nn = i >> 7, kk = i & 127;
        float v = in[kk * 128 + nn];
        __nv_bfloat16 h = __float2bfloat16(v);
        oh[i] = h;
        ol[i] = __float2bfloat16(v - __bfloat162float(h));
    }
}

// ---------------- mma.sync node GEMM (bf16 hi/lo split, fp32 accum) ----------------
#define LDA 136
#define SM_MAT (128 * LDA)
#define SMEM_TOTAL (4 * SM_MAT * 2)

__device__ __forceinline__ void mma_bf16(float* c, const uint32_t* a, const uint32_t* b) {
    asm volatile(
        "mma.sync.aligned.m16n8k16.row.col.f32.bf16.bf16.f32 "
        "{%0,%1,%2,%3}, {%4,%5,%6,%7}, {%8,%9}, {%0,%1,%2,%3};"
        : "+f"(c[0]), "+f"(c[1]), "+f"(c[2]), "+f"(c[3])
        : "r"(a[0]), "r"(a[1]), "r"(a[2]), "r"(a[3]), "r"(b[0]), "r"(b[1]));
}

__global__ __launch_bounds__(256, 1) void mmagemm_kernel(
    const float* __restrict__ X0,
    const __nv_bfloat16* __restrict__ Bh0, const __nv_bfloat16* __restrict__ Bl0,
    const float* __restrict__ X1,
    const __nv_bfloat16* __restrict__ Bh1, const __nv_bfloat16* __restrict__ Bl1,
    const float* __restrict__ X2,
    const __nv_bfloat16* __restrict__ Bh2, const __nv_bfloat16* __restrict__ Bl2,
    const float* __restrict__ bias, float* __restrict__ out, int n, int nterms) {
    extern __shared__ __nv_bfloat16 smem[];
    __nv_bfloat16* Ah = smem;
    __nv_bfloat16* Al = smem + SM_MAT;
    __nv_bfloat16* Bh = smem + 2 * SM_MAT;
    __nv_bfloat16* Bl = smem + 3 * SM_MAT;

    int tid = threadIdx.x;
    int wid = tid >> 5;
    int lane = tid & 31;
    int m0 = blockIdx.x * 128;

    const float* Xa[3] = {X0, X1, X2};
    const __nv_bfloat16* Bha[3] = {Bh0, Bh1, Bh2};
    const __nv_bfloat16* Bla[3] = {Bl0, Bl1, Bl2};

    int arow = tid >> 1;
    int akh = (tid & 1) * 64;
    int gma = m0 + arow;
    bool avalid = gma < n;

    int wr = (wid & 3) * 32;
    int wc = (wid >> 2) * 64;
    int g = lane >> 2;
    int tg = lane & 3;

    float acc[2][8][4];
#pragma unroll
    for (int mt = 0; mt < 2; ++mt)
#pragma unroll
        for (int nt = 0; nt < 8; ++nt)
#pragma unroll
            for (int q = 0; q < 4; ++q) acc[mt][nt][q] = 0.f;

    for (int t = 0; t < nterms; ++t) {
        __syncthreads();
        {
            const float* X = Xa[t];
            const float* xrow = X + (size_t)gma * 128 + akh;
            int base = arow * LDA + akh;
#pragma unroll
            for (int c = 0; c < 8; ++c) {
                float4 v0 = make_float4(0.f, 0.f, 0.f, 0.f), v1 = v0;
                if (avalid) {
                    v0 = *(const float4*)(xrow + c * 8);
                    v1 = *(const float4*)(xrow + c * 8 + 4);
                }
                __nv_bfloat162 h0 = __floats2bfloat162_rn(v0.x, v0.y);
                __nv_bfloat162 h1 = __floats2bfloat162_rn(v0.z, v0.w);
                __nv_bfloat162 h2 = __floats2bfloat162_rn(v1.x, v1.y);
                __nv_bfloat162 h3 = __floats2bfloat162_rn(v1.z, v1.w);
                float2 f0 = __bfloat1622float2(h0), f1 = __bfloat1622float2(h1);
                float2 f2 = __bfloat1622float2(h2), f3 = __bfloat1622float2(h3);
                __nv_bfloat162 l0 = __floats2bfloat162_rn(v0.x - f0.x, v0.y - f0.y);
                __nv_bfloat162 l1 = __floats2bfloat162_rn(v0.z - f1.x, v0.w - f1.y);
                __nv_bfloat162 l2 = __floats2bfloat162_rn(v1.x - f2.x, v1.y - f2.y);
                __nv_bfloat162 l3 = __floats2bfloat162_rn(v1.z - f3.x, v1.w - f3.y);
                uint4 hv, lv;
                hv.x = *(uint32_t*)&h0; hv.y = *(uint32_t*)&h1;
                hv.z = *(uint32_t*)&h2; hv.w = *(uint32_t*)&h3;
                lv.x = *(uint32_t*)&l0; lv.y = *(uint32_t*)&l1;
                lv.z = *(uint32_t*)&l2; lv.w = *(uint32_t*)&l3;
                *(uint4*)&Ah[base + c * 8] = hv;
                *(uint4*)&Al[base + c * 8] = lv;
            }
        }
        {
            const __nv_bfloat16* bh = Bha[t];
            const __nv_bfloat16* bl = Bla[t];
#pragma unroll
            for (int c = 0; c < 8; ++c) {
                int chunk = c * 256 + tid;
                int row = chunk >> 4;
                int k0 = (chunk & 15) * 8;
                int d = row * LDA + k0;
                *(uint4*)&Bh[d] = *(const uint4*)(bh + (size_t)chunk * 8);
                *(uint4*)&Bl[d] = *(const uint4*)(bl + (size_t)chunk * 8);
            }
        }
        __syncthreads();
#pragma unroll
        for (int ks = 0; ks < 8; ++ks) {
            int kb = ks * 16;
            uint32_t ah[2][4], al[2][4], bhf[8][2], blf[8][2];
#pragma unroll
            for (int mt = 0; mt < 2; ++mt) {
                int r = wr + mt * 16 + g;
                int o0 = r * LDA + kb + tg * 2;
                int o1 = (r + 8) * LDA + kb + tg * 2;
                ah[mt][0] = *(uint32_t*)&Ah[o0];
                ah[mt][1] = *(uint32_t*)&Ah[o1];
                ah[mt][2] = *(uint32_t*)&Ah[o0 + 8];
                ah[mt][3] = *(uint32_t*)&Ah[o1 + 8];
                al[mt][0] = *(uint32_t*)&Al[o0];
                al[mt][1] = *(uint32_t*)&Al[o1];
                al[mt][2] = *(uint32_t*)&Al[o0 + 8];
                al[mt][3] = *(uint32_t*)&Al[o1 + 8];
            }
#pragma unroll
            for (int nt = 0; nt < 8; ++nt) {
                int c = wc + nt * 8 + g;
                int o = c * LDA + kb + tg * 2;
                bhf[nt][0] = *(uint32_t*)&Bh[o];
                bhf[nt][1] = *(uint32_t*)&Bh[o + 8];
                blf[nt][0] = *(uint32_t*)&Bl[o];
                blf[nt][1] = *(uint32_t*)&Bl[o + 8];
            }
#pragma unroll
            for (int mt = 0; mt < 2; ++mt)
#pragma unroll
                for (int nt = 0; nt < 8; ++nt) {
                    mma_bf16(acc[mt][nt], ah[mt], bhf[nt]);
                    mma_bf16(acc[mt][nt], ah[mt], blf[nt]);
                    mma_bf16(acc[mt][nt], al[mt], bhf[nt]);
                }
        }
    }

#pragma unroll
    for (int mt = 0; mt < 2; ++mt) {
        int r0v = m0 + wr + mt * 16 + g;
        int r1v = r0v + 8;
#pragma unroll
        for (int nt = 0; nt < 8; ++nt) {
            int col = wc + nt * 8 + tg * 2;
            float b0 = __ldg(&bias[col]);
            float b1 = __ldg(&bias[col + 1]);
            if (r0v < n) {
                float2 o = make_float2(acc[mt][nt][0] + b0, acc[mt][nt][1] + b1);
                *(float2*)&out[(size_t)r0v * 128 + col] = o;
            }
            if (r1v < n) {
                float2 o = make_float2(acc[mt][nt][2] + b0, acc[mt][nt][3] + b1);
                *(float2*)&out[(size_t)r1v * 128 + col] = o;
            }
        }
    }
}

// ---------------- bias combine ----------------
__global__ void bias_combine_kernel(const float* __restrict__ bd1, const float* __restrict__ bs1,
                                    const float* __restrict__ bu1, const float* __restrict__ Wu1,
                                    const float* __restrict__ bd2, const float* __restrict__ bs2,
                                    const float* __restrict__ bu2, const float* __restrict__ Wu2) {
    int layer = blockIdx.x >> 1;
    int which = blockIdx.x & 1;
    int h = threadIdx.x;
    const float* bd = layer ? bd2 : bd1;
    const float* bs = layer ? bs2 : bs1;
    const float* bu = layer ? bu2 : bu1;
    const float* Wu = layer ? Wu2 : Wu1;
    auto cfun = [&](int i) {
        float s = bu[i * 128 + h];
        const float* wt = Wu + (size_t)i * 32768;
        for (int k = 0; k < 128; ++k) s = fmaf(bd[i * 128 + k], wt[k * 128 + h], s);
        const float* wb = wt + 16384;
        for (int k = 0; k < 128; ++k) s = fmaf(bs[i * 128 + k], wb[k * 128 + h], s);
        return s;
    };
    if (which == 0)
        d_bg[layer][h] = 0.5f * (cfun(0) + cfun(2));
    else
        d_bd[layer][h] = cfun(1);
}

// ---------------- batch norm ----------------
__global__ void zero4_kernel(float4* p, int n4) {
    int i = blockIdx.x * blockDim.x + threadIdx.x;
    if (i < n4) p[i] = make_float4(0.f, 0.f, 0.f, 0.f);
}
__global__ void bn_stats_kernel(const float* __restrict__ x, int n,
                                float* __restrict__ sum, float* __restrict__ sumsq) {
    int c = threadIdx.x;
    int r0 = blockIdx.x * 128;
    int rend = min(r0 + 128, n);
    float s = 0.f, s2 = 0.f;
    for (int r = r0; r < rend; ++r) {
        float v = x[(size_t)r * 128 + c];
        s += v;
        s2 = fmaf(v, v, s2);
    }
    atomicAdd(&sum[c], s);
    atomicAdd(&sumsq[c], s2);
}
__global__ void bn_final_kernel(const float* __restrict__ gamma, const float* __restrict__ beta) {
    int idx = blockIdx.x;
    int c = threadIdx.x;
    float nn = (idx == 0) ? (float)NG : (float)ND;
    float mean = d_bn_sum[idx * 128 + c] / nn;
    float var = d_bn_sumsq[idx * 128 + c] / nn - mean * mean;
    float sc = gamma[idx * 128 + c] * rsqrtf(var + 1e-5f);
    d_bn_scale[idx][c] = sc;
    d_bn_shift[idx][c] = beta[idx * 128 + c] - mean * sc;
}
__global__ void bn_apply_kernel(float* __restrict__ x, int n, int which) {
    int i = blockIdx.x * blockDim.x + threadIdx.x;
    if (i >= n * 32) return;
    int q = i & 31;
    int c = q * 4;
    const float* sc = d_bn_scale[which];
    const float* sh = d_bn_shift[which];
    float4 v = *(float4*)&x[(size_t)i * 4];
    v.x = fmaf(v.x, sc[c + 0], sh[c + 0]);
    v.y = fmaf(v.y, sc[c + 1], sh[c + 1]);
    v.z = fmaf(v.z, sc[c + 2], sh[c + 2]);
    v.w = fmaf(v.w, sc[c + 3], sh[c + 3]);
    v.x = v.x >= 0.f ? v.x : 0.01f * v.x;
    v.y = v.y >= 0.f ? v.y : 0.01f * v.y;
    v.z = v.z >= 0.f ? v.z : 0.01f * v.z;
    v.w = v.w >= 0.f ? v.w : 0.01f * v.w;
    *(float4*)&x[(size_t)i * 4] = v;
}

// ---------------- decoder ----------------
__global__ void decode_kernel(const int* __restrict__ ls, const int* __restrict__ ld,
                              float* __restrict__ out) {
    int gw = (blockIdx.x * blockDim.x + threadIdx.x) >> 5;
    int lane = threadIdx.x & 31;
    if (gw >= ELAB) return;
    int a = __ldg(&ls[gw]);
    int b = __ldg(&ld[gw]);
    float4 u = *(const float4*)&d_g2[(size_t)a * 128 + lane * 4];
    float4 v = *(const float4*)&d_d2[(size_t)b * 128 + lane * 4];
    float s = u.x * v.x + u.y * v.y + u.z * v.z + u.w * v.w;
#pragma unroll
    for (int o = 16; o; o >>= 1) s += __shfl_xor_sync(0xFFFFFFFFu, s, o);
    if (lane == 0) out[gw] = s;
}

// ---------------- launch ----------------
static inline int cdiv(int a, int b) { return (a + b - 1) / b; }

extern "C" void kernel_launch(void* const* d_in, const int* in_sizes, int n_in,
                              void* d_out, int out_size) {
    const float* x_gene = (const float*)d_in[0];
    const float* x_dis  = (const float*)d_in[1];
    const float* W_dst1 = (const float*)d_in[2];
    const float* W_src1 = (const float*)d_in[3];
    const float* W_upd1 = (const float*)d_in[4];
    const float* b_dst1 = (const float*)d_in[5];
    const float* b_src1 = (const float*)d_in[6];
    const float* b_upd1 = (const float*)d_in[7];
    const float* W_dst2 = (const float*)d_in[8];
    const float* W_src2 = (const float*)d_in[9];
    const float* W_upd2 = (const float*)d_in[10];
    const float* b_dst2 = (const float*)d_in[11];
    const float* b_src2 = (const float*)d_in[12];
    const float* b_upd2 = (const float*)d_in[13];
    const float* bn_gamma = (const float*)d_in[14];
    const float* bn_beta  = (const float*)d_in[15];
    const int* gg_src  = (const int*)d_in[16];
    const int* gg_dst  = (const int*)d_in[17];
    const int* gda_src = (const int*)d_in[18];
    const int* gda_dst = (const int*)d_in[19];
    const int* label_src = (const int*)d_in[20];
    const int* label_dst = (const int*)d_in[21];
    float* out = (float*)d_out;

    static bool attr_set = false;
    if (!attr_set) {
        cudaFuncSetAttribute(mmagemm_kernel, cudaFuncAttributeMaxDynamicSharedMemorySize, SMEM_TOTAL);
        attr_set = true;
    }

    float *agg_gg, *agg_rev, *agg_d, *g1, *d1, *g2, *d2, *rdgg, *rdrev, *rdd;
    float *Wc, *bg, *bd, *bnsum, *bnsumsq;
    __nv_bfloat16 *Wh, *Wl;
    int *ideg, *ptr_gg, *ptr_d, *ptr_rev, *idx_gg, *idx_d, *idx_rev;
    cudaGetSymbolAddress((void**)&agg_gg, d_agg_gg);
    cudaGetSymbolAddress((void**)&agg_rev, d_agg_rev);
    cudaGetSymbolAddress((void**)&agg_d, d_agg_d);
    cudaGetSymbolAddress((void**)&g1, d_g1);
    cudaGetSymbolAddress((void**)&d1, d_d1);
    cudaGetSymbolAddress((void**)&g2, d_g2);
    cudaGetSymbolAddress((void**)&d2, d_d2);
    cudaGetSymbolAddress((void**)&rdgg, d_rdeg_gg);
    cudaGetSymbolAddress((void**)&rdrev, d_rdeg_rev);
    cudaGetSymbolAddress((void**)&rdd, d_rdeg_d);
    cudaGetSymbolAddress((void**)&Wc, d_Wc);
    cudaGetSymbolAddress((void**)&Wh, d_Wh);
    cudaGetSymbolAddress((void**)&Wl, d_Wl);
    cudaGetSymbolAddress((void**)&bg, d_bg);
    cudaGetSymbolAddress((void**)&bd, d_bd);
    cudaGetSymbolAddress((void**)&bnsum, d_bn_sum);
    cudaGetSymbolAddress((void**)&bnsumsq, d_bn_sumsq);
    cudaGetSymbolAddress((void**)&ideg, d_ideg);
    cudaGetSymbolAddress((void**)&ptr_gg, d_ptr_gg);
    cudaGetSymbolAddress((void**)&ptr_d, d_ptr_d);
    cudaGetSymbolAddress((void**)&ptr_rev, d_ptr_rev);
    cudaGetSymbolAddress((void**)&idx_gg, d_idx_gg);
    cudaGetSymbolAddress((void**)&idx_d, d_idx_d);
    cudaGetSymbolAddress((void**)&idx_rev, d_idx_rev);

    const int MM = 16384;
    const int WU = 32768;
    const int WUB = 16384;
    const int NTOT = NG + ND + NG;

    // ---- CSR build (1-5) ----
    zero_int_kernel<<<cdiv(NTOT, 256), 256>>>(ideg, NTOT);
    deg_all_kernel<<<cdiv(ETOT, 256), 256>>>(gg_dst, gda_dst, gda_src, ideg);
    scan_all_kernel<<<3, 1024>>>();
    fill_all_kernel<<<cdiv(ETOT, 256), 256>>>(gg_src, gg_dst, gda_src, gda_dst);
    rdeg_all_kernel<<<cdiv(NTOT, 256), 256>>>();

    // ---- layer 1 aggregation (launch 6 = profiled slot) ----
    gather_kernel<<<cdiv(NG, 8), 256>>>(x_gene, ptr_gg, idx_gg, rdgg, agg_gg, NG);
    gather_kernel<<<cdiv(ND, 8), 256>>>(x_gene, ptr_d, idx_d, rdd, agg_d, ND);
    gather_kernel<<<cdiv(NG, 8), 256>>>(x_dis, ptr_rev, idx_rev, rdrev, agg_rev, NG);

    // ---- combine weights ----
    const float* Wd[2] = {W_dst1, W_dst2};
    const float* Ws[2] = {W_src1, W_src2};
    const float* Wu[2] = {W_upd1, W_upd2};
    for (int l = 0; l < 2; ++l) {
        float* base = Wc + (size_t)l * 5 * MM;
        fgemm_kernel<<<1, 256>>>(Wd[l] + 0 * MM, Wu[l] + 0 * WU,
                                 Wd[l] + 2 * MM, Wu[l] + 2 * WU, 0.5f, base + 0 * MM, 128);
        fgemm_kernel<<<1, 256>>>(Ws[l] + 0 * MM, Wu[l] + 0 * WU + WUB,
                                 nullptr, nullptr, 0.5f, base + 1 * MM, 128);
        fgemm_kernel<<<1, 256>>>(Ws[l] + 2 * MM, Wu[l] + 2 * WU + WUB,
                                 nullptr, nullptr, 0.5f, base + 2 * MM, 128);
        fgemm_kernel<<<1, 256>>>(Wd[l] + 1 * MM, Wu[l] + 1 * WU,
                                 nullptr, nullptr, 1.0f, base + 3 * MM, 128);
        fgemm_kernel<<<1, 256>>>(Ws[l] + 1 * MM, Wu[l] + 1 * WU + WUB,
                                 nullptr, nullptr, 1.0f, base + 4 * MM, 128);
    }
    wsplit_kernel<<<10, 256>>>(Wc, Wh, Wl);
    bias_combine_kernel<<<4, 128>>>(b_dst1, b_src1, b_upd1, W_upd1,
                                    b_dst2, b_src2, b_upd2, W_upd2);

    const int GB = cdiv(NG, 128), DB = cdiv(ND, 128);
    auto WHp = [&](int l, int j) { return Wh + (size_t)(l * 5 + j) * MM; };
    auto WLp = [&](int l, int j) { return Wl + (size_t)(l * 5 + j) * MM; };

    // ---- layer 1 GEMMs ----
    mmagemm_kernel<<<GB, 256, SMEM_TOTAL>>>(
        x_gene, WHp(0, 0), WLp(0, 0),
        agg_gg, WHp(0, 1), WLp(0, 1),
        agg_rev, WHp(0, 2), WLp(0, 2),
        bg, g1, NG, 3);
    mmagemm_kernel<<<DB, 256, SMEM_TOTAL>>>(
        x_dis, WHp(0, 3), WLp(0, 3),
        agg_d, WHp(0, 4), WLp(0, 4),
        nullptr, nullptr, nullptr,
        bd, d1, ND, 2);

    // ---- BN + leaky relu ----
    zero4_kernel<<<1, 64>>>((float4*)bnsum, 64);
    zero4_kernel<<<1, 64>>>((float4*)bnsumsq, 64);
    bn_stats_kernel<<<GB, 128>>>(g1, NG, bnsum, bnsumsq);
    bn_stats_kernel<<<DB, 128>>>(d1, ND, bnsum + 128, bnsumsq + 128);
    bn_final_kernel<<<2, 128>>>(bn_gamma, bn_beta);
    bn_apply_kernel<<<cdiv(NG * 32, 256), 256>>>(g1, NG, 0);
    bn_apply_kernel<<<cdiv(ND * 32, 256), 256>>>(d1, ND, 1);

    // ---- layer 2 aggregation ----
    gather_kernel<<<cdiv(NG, 8), 256>>>(g1, ptr_gg, idx_gg, rdgg, agg_gg, NG);
    gather_kernel<<<cdiv(ND, 8), 256>>>(g1, ptr_d, idx_d, rdd, agg_d, ND);
    gather_kernel<<<cdiv(NG, 8), 256>>>(d1, ptr_rev, idx_rev, rdrev, agg_rev, NG);

    // ---- layer 2 GEMMs ----
    mmagemm_kernel<<<GB, 256, SMEM_TOTAL>>>(
        g1, WHp(1, 0), WLp(1, 0),
        agg_gg, WHp(1, 1), WLp(1, 1),
        agg_rev, WHp(1, 2), WLp(1, 2),
        bg + HD, g2, NG, 3);
    mmagemm_kernel<<<DB, 256, SMEM_TOTAL>>>(
        d1, WHp(1, 3), WLp(1, 3),
        agg_d, WHp(1, 4), WLp(1, 4),
        nullptr, nullptr, nullptr,
        bd + HD, d2, ND, 2);

    // ---- decoder ----
    decode_kernel<<<cdiv(ELAB * 32, 256), 256>>>(label_src, label_dst, out);
}

// round 6
// speedup vs baseline: 2.2086x; 1.7579x over previous
#include <cuda_runtime.h>
#include <cuda_bf16.h>
#include <cstdint>
#include <cstddef>

#define NG 50000
#define ND 20000
#define HD 128
#define EGG 800000
#define EGDA 400000
#define ELAB 200000
#define ETOT (EGG + 2 * EGDA)
#define NTOT (NG + ND + NG)
#define MM 16384
#define WU 32768
#define WUB 16384

// ---------------- scratch ----------------
__device__ float d_agg_gg[(size_t)NG * HD];
__device__ float d_agg_rev[(size_t)NG * HD];
__device__ float d_agg_d[(size_t)ND * HD];
__device__ float d_g1[(size_t)NG * HD];
__device__ float d_d1[(size_t)ND * HD];
__device__ float d_g2[(size_t)NG * HD];
__device__ float d_d2[(size_t)ND * HD];
__device__ float d_rdeg_gg[NG];
__device__ float d_rdeg_rev[NG];
__device__ float d_rdeg_d[ND];
__device__ int d_ideg[NTOT];
__device__ int d_ptr_gg[NG + 1];
__device__ int d_ptr_d[ND + 1];
__device__ int d_ptr_rev[NG + 1];
__device__ int d_cur_gg[NG];
__device__ int d_cur_d[ND];
__device__ int d_cur_rev[NG];
__device__ int d_idx_gg[EGG];
__device__ int d_idx_d[EGDA];
__device__ int d_idx_rev[EGDA];
__device__ __nv_bfloat16 d_Wh[10 * MM];
__device__ __nv_bfloat16 d_Wl[10 * MM];
__device__ float d_bg[2][HD];
__device__ float d_bd[2][HD];
__device__ float d_bn_acc[512];   // [sum_g | sum_d | sq_g | sq_d]
__device__ float d_bn_scale[2][HD];
__device__ float d_bn_shift[2][HD];

// ---------------- init: zero ideg + bn accumulators ----------------
__global__ void init_kernel() {
    int i = blockIdx.x * blockDim.x + threadIdx.x;
    if (i < NTOT) d_ideg[i] = 0;
    else if (i < NTOT + 512) d_bn_acc[i - NTOT] = 0.f;
}

__global__ void deg_all_kernel(const int* __restrict__ gg_dst, const int* __restrict__ gda_dst,
                               const int* __restrict__ gda_src) {
    int i = blockIdx.x * blockDim.x + threadIdx.x;
    if (i < EGG) {
        atomicAdd(&d_ideg[__ldg(&gg_dst[i])], 1);
    } else if (i < EGG + EGDA) {
        atomicAdd(&d_ideg[NG + __ldg(&gda_dst[i - EGG])], 1);
    } else if (i < ETOT) {
        atomicAdd(&d_ideg[NG + ND + __ldg(&gda_src[i - EGG - EGDA])], 1);
    }
}

// chunked exclusive scan + rdeg, one block (1024 threads) per relation
__global__ void scan_all_kernel() {
    __shared__ int sm[1024];
    int rel = blockIdx.x;
    const int* deg;
    int n;
    int* ptr;
    int* cur;
    float* rdeg;
    if (rel == 0) { deg = d_ideg; n = NG; ptr = d_ptr_gg; cur = d_cur_gg; rdeg = d_rdeg_gg; }
    else if (rel == 1) { deg = d_ideg + NG; n = ND; ptr = d_ptr_d; cur = d_cur_d; rdeg = d_rdeg_d; }
    else { deg = d_ideg + NG + ND; n = NG; ptr = d_ptr_rev; cur = d_cur_rev; rdeg = d_rdeg_rev; }
    int tid = threadIdx.x;
    int chunk = (n + 1023) >> 10;
    int lo = tid * chunk;
    int hi = min(lo + chunk, n);
    int s = 0;
    for (int i = lo; i < hi; ++i) s += deg[i];
    sm[tid] = s;
    __syncthreads();
    for (int off = 1; off < 1024; off <<= 1) {
        int v = 0;
        if (tid >= off) v = sm[tid - off];
        __syncthreads();
        sm[tid] += v;
        __syncthreads();
    }
    int run = sm[tid] - s;
    for (int i = lo; i < hi; ++i) {
        int dg = deg[i];
        ptr[i] = run;
        cur[i] = run;
        rdeg[i] = 1.0f / fmaxf((float)dg, 1.0f);
        run += dg;
    }
    if (tid == 1023) ptr[n] = sm[1023];
}

__global__ void fill_all_kernel(const int* __restrict__ gg_src, const int* __restrict__ gg_dst,
                                const int* __restrict__ gda_src, const int* __restrict__ gda_dst) {
    int i = blockIdx.x * blockDim.x + threadIdx.x;
    if (i < EGG) {
        int p = atomicAdd(&d_cur_gg[__ldg(&gg_dst[i])], 1);
        d_idx_gg[p] = __ldg(&gg_src[i]);
    } else if (i < EGG + EGDA) {
        int e = i - EGG;
        int p = atomicAdd(&d_cur_d[__ldg(&gda_dst[e])], 1);
        d_idx_d[p] = __ldg(&gda_src[e]);
    } else if (i < ETOT) {
        int e = i - EGG - EGDA;
        int p = atomicAdd(&d_cur_rev[__ldg(&gda_src[e])], 1);
        d_idx_rev[p] = __ldg(&gda_dst[e]);
    }
}

// ---------------- fused gather: all 3 relations, one launch ----------------
__global__ __launch_bounds__(256) void gather_all_kernel(const float* __restrict__ Xg,
                                                         const float* __restrict__ Xd) {
    int w = (blockIdx.x * blockDim.x + threadIdx.x) >> 5;
    int lane = threadIdx.x & 31;
    const float* X;
    const int* ptr;
    const int* idx;
    const float* rdeg;
    float* out;
    int r;
    if (w < NG) {
        X = Xg; ptr = d_ptr_gg; idx = d_idx_gg; rdeg = d_rdeg_gg; out = d_agg_gg; r = w;
    } else if (w < NG + ND) {
        X = Xg; ptr = d_ptr_d; idx = d_idx_d; rdeg = d_rdeg_d; out = d_agg_d; r = w - NG;
    } else if (w < NTOT) {
        X = Xd; ptr = d_ptr_rev; idx = d_idx_rev; rdeg = d_rdeg_rev; out = d_agg_rev; r = w - NG - ND;
    } else return;
    int s = __ldg(&ptr[r]);
    int e = __ldg(&ptr[r + 1]);
    float4 a0 = make_float4(0.f, 0.f, 0.f, 0.f);
    float4 a1 = a0, a2 = a0, a3 = a0;
    int j = s;
    for (; j + 3 < e; j += 4) {
        int n0 = __ldg(&idx[j]);
        int n1 = __ldg(&idx[j + 1]);
        int n2 = __ldg(&idx[j + 2]);
        int n3 = __ldg(&idx[j + 3]);
        float4 v0 = *(const float4*)&X[(size_t)n0 * HD + lane * 4];
        float4 v1 = *(const float4*)&X[(size_t)n1 * HD + lane * 4];
        float4 v2 = *(const float4*)&X[(size_t)n2 * HD + lane * 4];
        float4 v3 = *(const float4*)&X[(size_t)n3 * HD + lane * 4];
        a0.x += v0.x; a0.y += v0.y; a0.z += v0.z; a0.w += v0.w;
        a1.x += v1.x; a1.y += v1.y; a1.z += v1.z; a1.w += v1.w;
        a2.x += v2.x; a2.y += v2.y; a2.z += v2.z; a2.w += v2.w;
        a3.x += v3.x; a3.y += v3.y; a3.z += v3.z; a3.w += v3.w;
    }
    for (; j < e; ++j) {
        int n0 = __ldg(&idx[j]);
        float4 v0 = *(const float4*)&X[(size_t)n0 * HD + lane * 4];
        a0.x += v0.x; a0.y += v0.y; a0.z += v0.z; a0.w += v0.w;
    }
    float rr = __ldg(&rdeg[r]);
    float4 o;
    o.x = (a0.x + a1.x + a2.x + a3.x) * rr;
    o.y = (a0.y + a1.y + a2.y + a3.y) * rr;
    o.z = (a0.z + a1.z + a2.z + a3.z) * rr;
    o.w = (a0.w + a1.w + a2.w + a3.w) * rr;
    *(float4*)&out[(size_t)r * HD + lane * 4] = o;
}

// ---------------- fused weight prep: 10 blocks, combine + transpose + split ----------------
__global__ __launch_bounds__(256) void wprep_kernel(
    const float* __restrict__ Wd1, const float* __restrict__ Ws1, const float* __restrict__ Wu1,
    const float* __restrict__ Wd2, const float* __restrict__ Ws2, const float* __restrict__ Wu2,
    __nv_bfloat16* __restrict__ Wh, __nv_bfloat16* __restrict__ Wl) {
    __shared__ __align__(16) float Xs[16][132];
    __shared__ __align__(16) float Ws_[16][128];
    int mtx = blockIdx.x;
    int l = mtx / 5, j = mtx % 5;
    const float* Wdl = l ? Wd2 : Wd1;
    const float* Wsl = l ? Ws2 : Ws1;
    const float* Wul = l ? Wu2 : Wu1;
    const float* X0 = nullptr;
    const float* W0 = nullptr;
    const float* X1 = nullptr;
    const float* W1 = nullptr;
    float scale = 1.f;
    switch (j) {
        case 0: X0 = Wdl; W0 = Wul; X1 = Wdl + 2 * MM; W1 = Wul + 2 * WU; scale = 0.5f; break;
        case 1: X0 = Wsl; W0 = Wul + WUB; scale = 0.5f; break;
        case 2: X0 = Wsl + 2 * MM; W0 = Wul + 2 * WU + WUB; scale = 0.5f; break;
        case 3: X0 = Wdl + MM; W0 = Wul + WU; scale = 1.f; break;
        case 4: X0 = Wsl + MM; W0 = Wul + WU + WUB; scale = 1.f; break;
    }
    int tid = threadIdx.x;
    float acc[8][8];
#pragma unroll
    for (int i = 0; i < 8; ++i)
#pragma unroll
        for (int q = 0; q < 8; ++q) acc[i][q] = 0.f;
    const float* Xp[2] = {X0, X1};
    const float* Wp[2] = {W0, W1};
    int rA = tid >> 2, kq = tid & 3, krow = tid >> 4, cq = tid & 15;
    int tx = tid & 15, ty = tid >> 4;
    for (int t = 0; t < 2; ++t) {
        const float* X = Xp[t];
        if (!X) continue;
        const float* W = Wp[t];
        for (int kc = 0; kc < 8; ++kc) {
#pragma unroll
            for (int h = 0; h < 2; ++h) {
                int r = rA + h * 64;
                float4 v = *(const float4*)&X[(size_t)r * 128 + kc * 16 + kq * 4];
                Xs[kq * 4 + 0][r] = v.x;
                Xs[kq * 4 + 1][r] = v.y;
                Xs[kq * 4 + 2][r] = v.z;
                Xs[kq * 4 + 3][r] = v.w;
            }
#pragma unroll
            for (int h = 0; h < 2; ++h) {
                int c = cq + h * 16;
                *(float4*)&Ws_[krow][c * 4] = *(const float4*)&W[(size_t)(kc * 16 + krow) * 128 + c * 4];
            }
            __syncthreads();
#pragma unroll
            for (int k = 0; k < 16; ++k) {
                float a[8], b[8];
                *(float4*)&a[0] = *(const float4*)&Xs[k][ty * 8];
                *(float4*)&a[4] = *(const float4*)&Xs[k][ty * 8 + 4];
                *(float4*)&b[0] = *(const float4*)&Ws_[k][tx * 8];
                *(float4*)&b[4] = *(const float4*)&Ws_[k][tx * 8 + 4];
#pragma unroll
                for (int i = 0; i < 8; ++i)
#pragma unroll
                    for (int q = 0; q < 8; ++q) acc[i][q] = fmaf(a[i], b[q], acc[i][q]);
            }
            __syncthreads();
        }
    }
    // write transposed bf16 hi/lo: Wh[n][k]
    __nv_bfloat16* oh = Wh + (size_t)mtx * MM;
    __nv_bfloat16* ol = Wl + (size_t)mtx * MM;
#pragma unroll
    for (int i = 0; i < 8; ++i) {
        int krow2 = ty * 8 + i;
#pragma unroll
        for (int q = 0; q < 8; ++q) {
            int col = tx * 8 + q;
            float v = acc[i][q] * scale;
            __nv_bfloat16 h = __float2bfloat16(v);
            oh[col * 128 + krow2] = h;
            ol[col * 128 + krow2] = __float2bfloat16(v - __bfloat162float(h));
        }
    }
}

// ---------------- mma.sync node GEMM with ldmatrix ----------------
#define LDA 136
#define SM_MAT (128 * LDA)
#define SMEM_TOTAL (4 * SM_MAT * 2)

__device__ __forceinline__ void mma_bf16(float* c, const uint32_t* a, uint32_t b0, uint32_t b1) {
    asm volatile(
        "mma.sync.aligned.m16n8k16.row.col.f32.bf16.bf16.f32 "
        "{%0,%1,%2,%3}, {%4,%5,%6,%7}, {%8,%9}, {%0,%1,%2,%3};"
        : "+f"(c[0]), "+f"(c[1]), "+f"(c[2]), "+f"(c[3])
        : "r"(a[0]), "r"(a[1]), "r"(a[2]), "r"(a[3]), "r"(b0), "r"(b1));
}
__device__ __forceinline__ void ldm_x4(uint32_t* r, uint32_t saddr) {
    asm volatile("ldmatrix.sync.aligned.m8n8.x4.shared.b16 {%0,%1,%2,%3}, [%4];"
                 : "=r"(r[0]), "=r"(r[1]), "=r"(r[2]), "=r"(r[3]) : "r"(saddr));
}

__global__ __launch_bounds__(256, 1) void mmagemm_kernel(
    const float* __restrict__ Xg0, const float* __restrict__ Xg1, const float* __restrict__ Xg2,
    const float* __restrict__ Xd0, const float* __restrict__ Xd1,
    const __nv_bfloat16* __restrict__ WhL, const __nv_bfloat16* __restrict__ WlL,
    const float* __restrict__ biasg, const float* __restrict__ biasd,
    float* __restrict__ outg, float* __restrict__ outd, int gb) {
    extern __shared__ __nv_bfloat16 smem[];
    __nv_bfloat16* Ah = smem;
    __nv_bfloat16* Al = smem + SM_MAT;
    __nv_bfloat16* Bh = smem + 2 * SM_MAT;
    __nv_bfloat16* Bl = smem + 3 * SM_MAT;

    int tid = threadIdx.x;
    int wid = tid >> 5;
    int lane = tid & 31;

    bool gene = (int)blockIdx.x < gb;
    int m0, n, nterms;
    const float* Xa[3];
    const __nv_bfloat16* Bha[3];
    const __nv_bfloat16* Bla[3];
    const float* bias;
    float* out;
    if (gene) {
        m0 = blockIdx.x * 128; n = NG; nterms = 3;
        Xa[0] = Xg0; Xa[1] = Xg1; Xa[2] = Xg2;
        Bha[0] = WhL; Bha[1] = WhL + MM; Bha[2] = WhL + 2 * MM;
        Bla[0] = WlL; Bla[1] = WlL + MM; Bla[2] = WlL + 2 * MM;
        bias = biasg; out = outg;
    } else {
        m0 = (blockIdx.x - gb) * 128; n = ND; nterms = 2;
        Xa[0] = Xd0; Xa[1] = Xd1; Xa[2] = Xd0;
        Bha[0] = WhL + 3 * MM; Bha[1] = WhL + 4 * MM; Bha[2] = WhL + 3 * MM;
        Bla[0] = WlL + 3 * MM; Bla[1] = WlL + 4 * MM; Bla[2] = WlL + 3 * MM;
        bias = biasd; out = outd;
    }

    int arow = tid >> 1;
    int akh = (tid & 1) * 64;
    int gma = m0 + arow;
    bool avalid = gma < n;

    int wr = (wid & 3) * 32;
    int wc = (wid >> 2) * 64;
    int g = lane >> 2;
    int tg = lane & 3;

    // shared-space base addresses
    uint32_t sAh = (uint32_t)__cvta_generic_to_shared(Ah);
    uint32_t sAl = (uint32_t)__cvta_generic_to_shared(Al);
    uint32_t sBh = (uint32_t)__cvta_generic_to_shared(Bh);
    uint32_t sBl = (uint32_t)__cvta_generic_to_shared(Bl);
    // ldmatrix per-lane offsets (bytes)
    // A x4 tiles: (mlo,klo),(mhi,klo),(mlo,khi),(mhi,khi)
    uint32_t aoff[2];
#pragma unroll
    for (int mt = 0; mt < 2; ++mt) {
        int row = wr + mt * 16 + ((lane >> 3) & 1) * 8 + (lane & 7);
        int kc = (lane >> 4) * 8;
        aoff[mt] = (uint32_t)((row * LDA + kc) * 2);
    }
    // B x4 tiles: (n lo, klo),(n lo, khi),(n hi, klo),(n hi, khi); covers nt=2m,2m+1
    uint32_t boff[4];
#pragma unroll
    for (int m = 0; m < 4; ++m) {
        int nn = wc + m * 16 + ((lane >> 4) & 1) * 8 + (lane & 7);
        int kc = ((lane >> 3) & 1) * 8;
        boff[m] = (uint32_t)((nn * LDA + kc) * 2);
    }

    float acc[2][8][4];
#pragma unroll
    for (int mt = 0; mt < 2; ++mt)
#pragma unroll
        for (int nt = 0; nt < 8; ++nt)
#pragma unroll
            for (int q = 0; q < 4; ++q) acc[mt][nt][q] = 0.f;

    for (int t = 0; t < nterms; ++t) {
        __syncthreads();
        {   // A tile: fp32 -> bf16 hi/lo
            const float* X = Xa[t];
            const float* xrow = X + (size_t)gma * 128 + akh;
            int base = arow * LDA + akh;
#pragma unroll
            for (int c = 0; c < 8; ++c) {
                float4 v0 = make_float4(0.f, 0.f, 0.f, 0.f), v1 = v0;
                if (avalid) {
                    v0 = *(const float4*)(xrow + c * 8);
                    v1 = *(const float4*)(xrow + c * 8 + 4);
                }
                __nv_bfloat162 h0 = __floats2bfloat162_rn(v0.x, v0.y);
                __nv_bfloat162 h1 = __floats2bfloat162_rn(v0.z, v0.w);
                __nv_bfloat162 h2 = __floats2bfloat162_rn(v1.x, v1.y);
                __nv_bfloat162 h3 = __floats2bfloat162_rn(v1.z, v1.w);
                float2 f0 = __bfloat1622float2(h0), f1 = __bfloat1622float2(h1);
                float2 f2 = __bfloat1622float2(h2), f3 = __bfloat1622float2(h3);
                __nv_bfloat162 l0 = __floats2bfloat162_rn(v0.x - f0.x, v0.y - f0.y);
                __nv_bfloat162 l1 = __floats2bfloat162_rn(v0.z - f1.x, v0.w - f1.y);
                __nv_bfloat162 l2 = __floats2bfloat162_rn(v1.x - f2.x, v1.y - f2.y);
                __nv_bfloat162 l3 = __floats2bfloat162_rn(v1.z - f3.x, v1.w - f3.y);
                uint4 hv, lv;
                hv.x = *(uint32_t*)&h0; hv.y = *(uint32_t*)&h1;
                hv.z = *(uint32_t*)&h2; hv.w = *(uint32_t*)&h3;
                lv.x = *(uint32_t*)&l0; lv.y = *(uint32_t*)&l1;
                lv.z = *(uint32_t*)&l2; lv.w = *(uint32_t*)&l3;
                *(uint4*)&Ah[base + c * 8] = hv;
                *(uint4*)&Al[base + c * 8] = lv;
            }
        }
        {   // B tile copy
            const __nv_bfloat16* bh = Bha[t];
            const __nv_bfloat16* bl = Bla[t];
#pragma unroll
            for (int c = 0; c < 8; ++c) {
                int chunk = c * 256 + tid;
                int row = chunk >> 4;
                int k0 = (chunk & 15) * 8;
                int d = row * LDA + k0;
                *(uint4*)&Bh[d] = *(const uint4*)(bh + (size_t)chunk * 8);
                *(uint4*)&Bl[d] = *(const uint4*)(bl + (size_t)chunk * 8);
            }
        }
        __syncthreads();
#pragma unroll
        for (int ks = 0; ks < 8; ++ks) {
            uint32_t kb2 = (uint32_t)(ks * 32);  // ks*16 elements * 2 bytes
            uint32_t ah[2][4], al[2][4], bh[4][4], bl[4][4];
            ldm_x4(ah[0], sAh + aoff[0] + kb2);
            ldm_x4(ah[1], sAh + aoff[1] + kb2);
            ldm_x4(al[0], sAl + aoff[0] + kb2);
            ldm_x4(al[1], sAl + aoff[1] + kb2);
#pragma unroll
            for (int m = 0; m < 4; ++m) {
                ldm_x4(bh[m], sBh + boff[m] + kb2);
                ldm_x4(bl[m], sBl + boff[m] + kb2);
            }
#pragma unroll
            for (int mt = 0; mt < 2; ++mt)
#pragma unroll
                for (int m = 0; m < 4; ++m) {
                    mma_bf16(acc[mt][2 * m], ah[mt], bh[m][0], bh[m][1]);
                    mma_bf16(acc[mt][2 * m], ah[mt], bl[m][0], bl[m][1]);
                    mma_bf16(acc[mt][2 * m], al[mt], bh[m][0], bh[m][1]);
                    mma_bf16(acc[mt][2 * m + 1], ah[mt], bh[m][2], bh[m][3]);
                    mma_bf16(acc[mt][2 * m + 1], ah[mt], bl[m][2], bl[m][3]);
                    mma_bf16(acc[mt][2 * m + 1], al[mt], bh[m][2], bh[m][3]);
                }
        }
    }

#pragma unroll
    for (int mt = 0; mt < 2; ++mt) {
        int r0v = m0 + wr + mt * 16 + g;
        int r1v = r0v + 8;
#pragma unroll
        for (int nt = 0; nt < 8; ++nt) {
            int col = wc + nt * 8 + tg * 2;
            float b0 = __ldg(&bias[col]);
            float b1 = __ldg(&bias[col + 1]);
            if (r0v < n) {
                float2 o = make_float2(acc[mt][nt][0] + b0, acc[mt][nt][1] + b1);
                *(float2*)&out[(size_t)r0v * 128 + col] = o;
            }
            if (r1v < n) {
                float2 o = make_float2(acc[mt][nt][2] + b0, acc[mt][nt][3] + b1);
                *(float2*)&out[(size_t)r1v * 128 + col] = o;
            }
        }
    }
}

// ---------------- bias combine ----------------
__global__ void bias_combine_kernel(const float* __restrict__ bd1, const float* __restrict__ bs1,
                                    const float* __restrict__ bu1, const float* __restrict__ Wu1,
                                    const float* __restrict__ bd2, const float* __restrict__ bs2,
                                    const float* __restrict__ bu2, const float* __restrict__ Wu2) {
    int layer = blockIdx.x >> 1;
    int which = blockIdx.x & 1;
    int h = threadIdx.x;
    const float* bd = layer ? bd2 : bd1;
    const float* bs = layer ? bs2 : bs1;
    const float* bu = layer ? bu2 : bu1;
    const float* Wu = layer ? Wu2 : Wu1;
    auto cfun = [&](int i) {
        float s = bu[i * 128 + h];
        const float* wt = Wu + (size_t)i * WU;
        for (int k = 0; k < 128; ++k) s = fmaf(bd[i * 128 + k], wt[k * 128 + h], s);
        const float* wb = wt + WUB;
        for (int k = 0; k < 128; ++k) s = fmaf(bs[i * 128 + k], wb[k * 128 + h], s);
        return s;
    };
    if (which == 0)
        d_bg[layer][h] = 0.5f * (cfun(0) + cfun(2));
    else
        d_bd[layer][h] = cfun(1);
}

// ---------------- batch norm (fused stats, final, fused apply) ----------------
__global__ void bn_stats_kernel(const float* __restrict__ xg, const float* __restrict__ xd, int gb) {
    int c = threadIdx.x;
    bool gene = (int)blockIdx.x < gb;
    const float* x = gene ? xg : xd;
    int nn = gene ? NG : ND;
    int b = gene ? blockIdx.x : (blockIdx.x - gb);
    int r0 = b * 128;
    int rend = min(r0 + 128, nn);
    float s = 0.f, s2 = 0.f;
    for (int r = r0; r < rend; ++r) {
        float v = x[(size_t)r * 128 + c];
        s += v;
        s2 = fmaf(v, v, s2);
    }
    int off = gene ? 0 : 128;
    atomicAdd(&d_bn_acc[off + c], s);
    atomicAdd(&d_bn_acc[256 + off + c], s2);
}
__global__ void bn_final_kernel(const float* __restrict__ gamma, const float* __restrict__ beta) {
    int idx = blockIdx.x;
    int c = threadIdx.x;
    float nn = (idx == 0) ? (float)NG : (float)ND;
    float mean = d_bn_acc[idx * 128 + c] / nn;
    float var = d_bn_acc[256 + idx * 128 + c] / nn - mean * mean;
    float sc = gamma[idx * 128 + c] * rsqrtf(var + 1e-5f);
    d_bn_scale[idx][c] = sc;
    d_bn_shift[idx][c] = beta[idx * 128 + c] - mean * sc;
}
__global__ void bn_apply_kernel(float* __restrict__ xg, float* __restrict__ xd) {
    int i = blockIdx.x * blockDim.x + threadIdx.x;  // float4 index over both tensors
    int which;
    float* x;
    if (i < NG * 32) { which = 0; x = xg; }
    else if (i < (NG + ND) * 32) { which = 1; x = xd; i -= NG * 32; }
    else return;
    int q = i & 31;
    int c = q * 4;
    const float* sc = d_bn_scale[which];
    const float* sh = d_bn_shift[which];
    float4 v = *(float4*)&x[(size_t)i * 4];
    v.x = fmaf(v.x, sc[c + 0], sh[c + 0]);
    v.y = fmaf(v.y, sc[c + 1], sh[c + 1]);
    v.z = fmaf(v.z, sc[c + 2], sh[c + 2]);
    v.w = fmaf(v.w, sc[c + 3], sh[c + 3]);
    v.x = v.x >= 0.f ? v.x : 0.01f * v.x;
    v.y = v.y >= 0.f ? v.y : 0.01f * v.y;
    v.z = v.z >= 0.f ? v.z : 0.01f * v.z;
    v.w = v.w >= 0.f ? v.w : 0.01f * v.w;
    *(float4*)&x[(size_t)i * 4] = v;
}

// ---------------- decoder ----------------
__global__ void decode_kernel(const int* __restrict__ ls, const int* __restrict__ ld,
                              float* __restrict__ out) {
    int gw = (blockIdx.x * blockDim.x + threadIdx.x) >> 5;
    int lane = threadIdx.x & 31;
    if (gw >= ELAB) return;
    int a = __ldg(&ls[gw]);
    int b = __ldg(&ld[gw]);
    float4 u = *(const float4*)&d_g2[(size_t)a * 128 + lane * 4];
    float4 v = *(const float4*)&d_d2[(size_t)b * 128 + lane * 4];
    float s = u.x * v.x + u.y * v.y + u.z * v.z + u.w * v.w;
#pragma unroll
    for (int o = 16; o; o >>= 1) s += __shfl_xor_sync(0xFFFFFFFFu, s, o);
    if (lane == 0) out[gw] = s;
}

// ---------------- launch ----------------
static inline int cdiv(int a, int b) { return (a + b - 1) / b; }

extern "C" void kernel_launch(void* const* d_in, const int* in_sizes, int n_in,
                              void* d_out, int out_size) {
    const float* x_gene = (const float*)d_in[0];
    const float* x_dis  = (const float*)d_in[1];
    const float* W_dst1 = (const float*)d_in[2];
    const float* W_src1 = (const float*)d_in[3];
    const float* W_upd1 = (const float*)d_in[4];
    const float* b_dst1 = (const float*)d_in[5];
    const float* b_src1 = (const float*)d_in[6];
    const float* b_upd1 = (const float*)d_in[7];
    const float* W_dst2 = (const float*)d_in[8];
    const float* W_src2 = (const float*)d_in[9];
    const float* W_upd2 = (const float*)d_in[10];
    const float* b_dst2 = (const float*)d_in[11];
    const float* b_src2 = (const float*)d_in[12];
    const float* b_upd2 = (const float*)d_in[13];
    const float* bn_gamma = (const float*)d_in[14];
    const float* bn_beta  = (const float*)d_in[15];
    const int* gg_src  = (const int*)d_in[16];
    const int* gg_dst  = (const int*)d_in[17];
    const int* gda_src = (const int*)d_in[18];
    const int* gda_dst = (const int*)d_in[19];
    const int* label_src = (const int*)d_in[20];
    const int* label_dst = (const int*)d_in[21];
    float* out = (float*)d_out;

    static bool attr_set = false;
    if (!attr_set) {
        cudaFuncSetAttribute(mmagemm_kernel, cudaFuncAttributeMaxDynamicSharedMemorySize, SMEM_TOTAL);
        attr_set = true;
    }

    float *agg_gg, *agg_rev, *agg_d, *g1, *d1, *g2, *d2, *bg, *bd;
    __nv_bfloat16 *Wh, *Wl;
    cudaGetSymbolAddress((void**)&agg_gg, d_agg_gg);
    cudaGetSymbolAddress((void**)&agg_rev, d_agg_rev);
    cudaGetSymbolAddress((void**)&agg_d, d_agg_d);
    cudaGetSymbolAddress((void**)&g1, d_g1);
    cudaGetSymbolAddress((void**)&d1, d_d1);
    cudaGetSymbolAddress((void**)&g2, d_g2);
    cudaGetSymbolAddress((void**)&d2, d_d2);
    cudaGetSymbolAddress((void**)&Wh, d_Wh);
    cudaGetSymbolAddress((void**)&Wl, d_Wl);
    cudaGetSymbolAddress((void**)&bg, d_bg);
    cudaGetSymbolAddress((void**)&bd, d_bd);

    const int GB = cdiv(NG, 128), DB = cdiv(ND, 128);

    // 1-4: CSR build
    init_kernel<<<cdiv(NTOT + 512, 256), 256>>>();
    deg_all_kernel<<<cdiv(ETOT, 256), 256>>>(gg_dst, gda_dst, gda_src);
    scan_all_kernel<<<3, 1024>>>();
    fill_all_kernel<<<cdiv(ETOT, 256), 256>>>(gg_src, gg_dst, gda_src, gda_dst);

    // 5: layer-1 aggregation (all 3 relations)
    gather_all_kernel<<<cdiv(NTOT * 32, 256), 256>>>(x_gene, x_dis);

    // 6-7: weight prep
    wprep_kernel<<<10, 256>>>(W_dst1, W_src1, W_upd1, W_dst2, W_src2, W_upd2, Wh, Wl);
    bias_combine_kernel<<<4, 128>>>(b_dst1, b_src1, b_upd1, W_upd1,
                                    b_dst2, b_src2, b_upd2, W_upd2);

    // 8: layer-1 GEMMs (gene + disease fused)
    mmagemm_kernel<<<GB + DB, 256, SMEM_TOTAL>>>(
        x_gene, agg_gg, agg_rev, x_dis, agg_d,
        Wh, Wl, bg, bd, g1, d1, GB);

    // 9-11: BN + leaky relu
    bn_stats_kernel<<<GB + DB, 128>>>(g1, d1, GB);
    bn_final_kernel<<<2, 128>>>(bn_gamma, bn_beta);
    bn_apply_kernel<<<cdiv((NG + ND) * 32, 256), 256>>>(g1, d1);

    // 12: layer-2 aggregation
    gather_all_kernel<<<cdiv(NTOT * 32, 256), 256>>>(g1, d1);

    // 13: layer-2 GEMMs
    mmagemm_kernel<<<GB + DB, 256, SMEM_TOTAL>>>(
        g1, agg_gg, agg_rev, d1, agg_d,
        Wh + 5 * MM, Wl + 5 * MM, bg + HD, bd + HD, g2, d2, GB);

    // 14: decoder
    decode_kernel<<<cdiv(ELAB * 32, 256), 256>>>(label_src, label_dst, out);
}

// round 7
// speedup vs baseline: 2.2804x; 1.0325x over previous
#include <cuda_runtime.h>
#include <cuda_bf16.h>
#include <cstdint>
#include <cstddef>

#define NG 50000
#define ND 20000
#define HD 128
#define EGG 800000
#define EGDA 400000
#define ELAB 200000
#define ETOT (EGG + 2 * EGDA)
#define NTOT (NG + ND + NG)
#define MM 16384
#define WU 32768
#define WUB 16384

// ---------------- scratch ----------------
__device__ float d_agg_gg[(size_t)NG * HD];
__device__ float d_agg_rev[(size_t)NG * HD];
__device__ float d_agg_d[(size_t)ND * HD];
__device__ float d_g1[(size_t)NG * HD];
__device__ float d_d1[(size_t)ND * HD];
__device__ float d_g2[(size_t)NG * HD];
__device__ float d_d2[(size_t)ND * HD];
__device__ __nv_bfloat16 d_xbf_g[(size_t)NG * HD];  // bf16 shadow of gathered gene table
__device__ __nv_bfloat16 d_xbf_d[(size_t)ND * HD];  // bf16 shadow of gathered disease table
__device__ float d_rdeg_gg[NG];
__device__ float d_rdeg_rev[NG];
__device__ float d_rdeg_d[ND];
__device__ int d_ideg[NTOT];
__device__ int d_ptr_gg[NG + 1];
__device__ int d_ptr_d[ND + 1];
__device__ int d_ptr_rev[NG + 1];
__device__ int d_cur_gg[NG];
__device__ int d_cur_d[ND];
__device__ int d_cur_rev[NG];
__device__ int d_idx_gg[EGG];
__device__ int d_idx_d[EGDA];
__device__ int d_idx_rev[EGDA];
__device__ __nv_bfloat16 d_Wh[10 * MM];
__device__ __nv_bfloat16 d_Wl[10 * MM];
__device__ float d_bg[2][HD];
__device__ float d_bd[2][HD];
__device__ float d_bn_acc[512];   // [sum_g | sum_d | sq_g | sq_d]
__device__ float d_bn_scale[2][HD];
__device__ float d_bn_shift[2][HD];

// ---------------- init: zero ideg + bn accumulators ----------------
__global__ void init_kernel() {
    int i = blockIdx.x * blockDim.x + threadIdx.x;
    if (i < NTOT) d_ideg[i] = 0;
    else if (i < NTOT + 512) d_bn_acc[i - NTOT] = 0.f;
}

__global__ void deg_all_kernel(const int* __restrict__ gg_dst, const int* __restrict__ gda_dst,
                               const int* __restrict__ gda_src) {
    int i = blockIdx.x * blockDim.x + threadIdx.x;
    if (i < EGG) {
        atomicAdd(&d_ideg[__ldg(&gg_dst[i])], 1);
    } else if (i < EGG + EGDA) {
        atomicAdd(&d_ideg[NG + __ldg(&gda_dst[i - EGG])], 1);
    } else if (i < ETOT) {
        atomicAdd(&d_ideg[NG + ND + __ldg(&gda_src[i - EGG - EGDA])], 1);
    }
}

// chunked exclusive scan + rdeg, one block (1024 threads) per relation
__global__ void scan_all_kernel() {
    __shared__ int sm[1024];
    int rel = blockIdx.x;
    const int* deg;
    int n;
    int* ptr;
    int* cur;
    float* rdeg;
    if (rel == 0) { deg = d_ideg; n = NG; ptr = d_ptr_gg; cur = d_cur_gg; rdeg = d_rdeg_gg; }
    else if (rel == 1) { deg = d_ideg + NG; n = ND; ptr = d_ptr_d; cur = d_cur_d; rdeg = d_rdeg_d; }
    else { deg = d_ideg + NG + ND; n = NG; ptr = d_ptr_rev; cur = d_cur_rev; rdeg = d_rdeg_rev; }
    int tid = threadIdx.x;
    int chunk = (n + 1023) >> 10;
    int lo = tid * chunk;
    int hi = min(lo + chunk, n);
    int s = 0;
    for (int i = lo; i < hi; ++i) s += deg[i];
    sm[tid] = s;
    __syncthreads();
    for (int off = 1; off < 1024; off <<= 1) {
        int v = 0;
        if (tid >= off) v = sm[tid - off];
        __syncthreads();
        sm[tid] += v;
        __syncthreads();
    }
    int run = sm[tid] - s;
    for (int i = lo; i < hi; ++i) {
        int dg = deg[i];
        ptr[i] = run;
        cur[i] = run;
        rdeg[i] = 1.0f / fmaxf((float)dg, 1.0f);
        run += dg;
    }
    if (tid == 1023) ptr[n] = sm[1023];
}

__global__ void fill_all_kernel(const int* __restrict__ gg_src, const int* __restrict__ gg_dst,
                                const int* __restrict__ gda_src, const int* __restrict__ gda_dst) {
    int i = blockIdx.x * blockDim.x + threadIdx.x;
    if (i < EGG) {
        int p = atomicAdd(&d_cur_gg[__ldg(&gg_dst[i])], 1);
        d_idx_gg[p] = __ldg(&gg_src[i]);
    } else if (i < EGG + EGDA) {
        int e = i - EGG;
        int p = atomicAdd(&d_cur_d[__ldg(&gda_dst[e])], 1);
        d_idx_d[p] = __ldg(&gda_src[e]);
    } else if (i < ETOT) {
        int e = i - EGG - EGDA;
        int p = atomicAdd(&d_cur_rev[__ldg(&gda_src[e])], 1);
        d_idx_rev[p] = __ldg(&gda_dst[e]);
    }
}

// ---------------- fp32 -> bf16 shadow tables (layer-1 inputs) ----------------
__global__ void tobf16_kernel(const float* __restrict__ xg, const float* __restrict__ xd) {
    int i = blockIdx.x * blockDim.x + threadIdx.x;  // 4-element chunks
    const float* x;
    __nv_bfloat16* o;
    if (i < NG * 32) { x = xg; o = d_xbf_g; }
    else if (i < (NG + ND) * 32) { x = xd; o = d_xbf_d; i -= NG * 32; }
    else return;
    float4 v = *(const float4*)&x[(size_t)i * 4];
    __nv_bfloat162 a = __floats2bfloat162_rn(v.x, v.y);
    __nv_bfloat162 b = __floats2bfloat162_rn(v.z, v.w);
    uint2 u;
    u.x = *(uint32_t*)&a;
    u.y = *(uint32_t*)&b;
    *(uint2*)&o[(size_t)i * 4] = u;
}

// ---------------- fused gather (bf16 reads): all 3 relations, one launch ----------------
__global__ __launch_bounds__(256) void gather_all_kernel(const __nv_bfloat16* __restrict__ Xg,
                                                         const __nv_bfloat16* __restrict__ Xd) {
    int w = (blockIdx.x * blockDim.x + threadIdx.x) >> 5;
    int lane = threadIdx.x & 31;
    const __nv_bfloat16* X;
    const int* ptr;
    const int* idx;
    const float* rdeg;
    float* out;
    int r;
    if (w < NG) {
        X = Xg; ptr = d_ptr_gg; idx = d_idx_gg; rdeg = d_rdeg_gg; out = d_agg_gg; r = w;
    } else if (w < NG + ND) {
        X = Xg; ptr = d_ptr_d; idx = d_idx_d; rdeg = d_rdeg_d; out = d_agg_d; r = w - NG;
    } else if (w < NTOT) {
        X = Xd; ptr = d_ptr_rev; idx = d_idx_rev; rdeg = d_rdeg_rev; out = d_agg_rev; r = w - NG - ND;
    } else return;
    int s = __ldg(&ptr[r]);
    int e = __ldg(&ptr[r + 1]);
    float4 a0 = make_float4(0.f, 0.f, 0.f, 0.f);
    float4 a1 = a0, a2 = a0, a3 = a0;
    int j = s;
    for (; j + 3 < e; j += 4) {
        int n0 = __ldg(&idx[j]);
        int n1 = __ldg(&idx[j + 1]);
        int n2 = __ldg(&idx[j + 2]);
        int n3 = __ldg(&idx[j + 3]);
        uint2 u0 = *(const uint2*)&X[(size_t)n0 * HD + lane * 4];
        uint2 u1 = *(const uint2*)&X[(size_t)n1 * HD + lane * 4];
        uint2 u2 = *(const uint2*)&X[(size_t)n2 * HD + lane * 4];
        uint2 u3 = *(const uint2*)&X[(size_t)n3 * HD + lane * 4];
        float2 p;
        p = __bfloat1622float2(*(__nv_bfloat162*)&u0.x); a0.x += p.x; a0.y += p.y;
        p = __bfloat1622float2(*(__nv_bfloat162*)&u0.y); a0.z += p.x; a0.w += p.y;
        p = __bfloat1622float2(*(__nv_bfloat162*)&u1.x); a1.x += p.x; a1.y += p.y;
        p = __bfloat1622float2(*(__nv_bfloat162*)&u1.y); a1.z += p.x; a1.w += p.y;
        p = __bfloat1622float2(*(__nv_bfloat162*)&u2.x); a2.x += p.x; a2.y += p.y;
        p = __bfloat1622float2(*(__nv_bfloat162*)&u2.y); a2.z += p.x; a2.w += p.y;
        p = __bfloat1622float2(*(__nv_bfloat162*)&u3.x); a3.x += p.x; a3.y += p.y;
        p = __bfloat1622float2(*(__nv_bfloat162*)&u3.y); a3.z += p.x; a3.w += p.y;
    }
    for (; j < e; ++j) {
        int n0 = __ldg(&idx[j]);
        uint2 u0 = *(const uint2*)&X[(size_t)n0 * HD + lane * 4];
        float2 p;
        p = __bfloat1622float2(*(__nv_bfloat162*)&u0.x); a0.x += p.x; a0.y += p.y;
        p = __bfloat1622float2(*(__nv_bfloat162*)&u0.y); a0.z += p.x; a0.w += p.y;
    }
    float rr = __ldg(&rdeg[r]);
    float4 o;
    o.x = (a0.x + a1.x + a2.x + a3.x) * rr;
    o.y = (a0.y + a1.y + a2.y + a3.y) * rr;
    o.z = (a0.z + a1.z + a2.z + a3.z) * rr;
    o.w = (a0.w + a1.w + a2.w + a3.w) * rr;
    *(float4*)&out[(size_t)r * HD + lane * 4] = o;
}

// ---------------- fused weight prep: 10 blocks, combine + transpose + split ----------------
__global__ __launch_bounds__(256) void wprep_kernel(
    const float* __restrict__ Wd1, const float* __restrict__ Ws1, const float* __restrict__ Wu1,
    const float* __restrict__ Wd2, const float* __restrict__ Ws2, const float* __restrict__ Wu2,
    __nv_bfloat16* __restrict__ Wh, __nv_bfloat16* __restrict__ Wl) {
    __shared__ __align__(16) float Xs[16][132];
    __shared__ __align__(16) float Ws_[16][128];
    int mtx = blockIdx.x;
    int l = mtx / 5, j = mtx % 5;
    const float* Wdl = l ? Wd2 : Wd1;
    const float* Wsl = l ? Ws2 : Ws1;
    const float* Wul = l ? Wu2 : Wu1;
    const float* X0 = nullptr;
    const float* W0 = nullptr;
    const float* X1 = nullptr;
    const float* W1 = nullptr;
    float scale = 1.f;
    switch (j) {
        case 0: X0 = Wdl; W0 = Wul; X1 = Wdl + 2 * MM; W1 = Wul + 2 * WU; scale = 0.5f; break;
        case 1: X0 = Wsl; W0 = Wul + WUB; scale = 0.5f; break;
        case 2: X0 = Wsl + 2 * MM; W0 = Wul + 2 * WU + WUB; scale = 0.5f; break;
        case 3: X0 = Wdl + MM; W0 = Wul + WU; scale = 1.f; break;
        case 4: X0 = Wsl + MM; W0 = Wul + WU + WUB; scale = 1.f; break;
    }
    int tid = threadIdx.x;
    float acc[8][8];
#pragma unroll
    for (int i = 0; i < 8; ++i)
#pragma unroll
        for (int q = 0; q < 8; ++q) acc[i][q] = 0.f;
    const float* Xp[2] = {X0, X1};
    const float* Wp[2] = {W0, W1};
    int rA = tid >> 2, kq = tid & 3, krow = tid >> 4, cq = tid & 15;
    int tx = tid & 15, ty = tid >> 4;
    for (int t = 0; t < 2; ++t) {
        const float* X = Xp[t];
        if (!X) continue;
        const float* W = Wp[t];
        for (int kc = 0; kc < 8; ++kc) {
#pragma unroll
            for (int h = 0; h < 2; ++h) {
                int r = rA + h * 64;
                float4 v = *(const float4*)&X[(size_t)r * 128 + kc * 16 + kq * 4];
                Xs[kq * 4 + 0][r] = v.x;
                Xs[kq * 4 + 1][r] = v.y;
                Xs[kq * 4 + 2][r] = v.z;
                Xs[kq * 4 + 3][r] = v.w;
            }
#pragma unroll
            for (int h = 0; h < 2; ++h) {
                int c = cq + h * 16;
                *(float4*)&Ws_[krow][c * 4] = *(const float4*)&W[(size_t)(kc * 16 + krow) * 128 + c * 4];
            }
            __syncthreads();
#pragma unroll
            for (int k = 0; k < 16; ++k) {
                float a[8], b[8];
                *(float4*)&a[0] = *(const float4*)&Xs[k][ty * 8];
                *(float4*)&a[4] = *(const float4*)&Xs[k][ty * 8 + 4];
                *(float4*)&b[0] = *(const float4*)&Ws_[k][tx * 8];
                *(float4*)&b[4] = *(const float4*)&Ws_[k][tx * 8 + 4];
#pragma unroll
                for (int i = 0; i < 8; ++i)
#pragma unroll
                    for (int q = 0; q < 8; ++q) acc[i][q] = fmaf(a[i], b[q], acc[i][q]);
            }
            __syncthreads();
        }
    }
    __nv_bfloat16* oh = Wh + (size_t)mtx * MM;
    __nv_bfloat16* ol = Wl + (size_t)mtx * MM;
#pragma unroll
    for (int i = 0; i < 8; ++i) {
        int krow2 = ty * 8 + i;
#pragma unroll
        for (int q = 0; q < 8; ++q) {
            int col = tx * 8 + q;
            float v = acc[i][q] * scale;
            __nv_bfloat16 h = __float2bfloat16(v);
            oh[col * 128 + krow2] = h;
            ol[col * 128 + krow2] = __float2bfloat16(v - __bfloat162float(h));
        }
    }
}

// ---------------- mma.sync node GEMM with ldmatrix ----------------
#define LDA 136
#define SM_MAT (128 * LDA)
#define SMEM_TOTAL (4 * SM_MAT * 2)

__device__ __forceinline__ void mma_bf16(float* c, const uint32_t* a, uint32_t b0, uint32_t b1) {
    asm volatile(
        "mma.sync.aligned.m16n8k16.row.col.f32.bf16.bf16.f32 "
        "{%0,%1,%2,%3}, {%4,%5,%6,%7}, {%8,%9}, {%0,%1,%2,%3};"
        : "+f"(c[0]), "+f"(c[1]), "+f"(c[2]), "+f"(c[3])
        : "r"(a[0]), "r"(a[1]), "r"(a[2]), "r"(a[3]), "r"(b0), "r"(b1));
}
__device__ __forceinline__ void ldm_x4(uint32_t* r, uint32_t saddr) {
    asm volatile("ldmatrix.sync.aligned.m8n8.x4.shared.b16 {%0,%1,%2,%3}, [%4];"
                 : "=r"(r[0]), "=r"(r[1]), "=r"(r[2]), "=r"(r[3]) : "r"(saddr));
}

__global__ __launch_bounds__(256, 1) void mmagemm_kernel(
    const float* __restrict__ Xg0, const float* __restrict__ Xg1, const float* __restrict__ Xg2,
    const float* __restrict__ Xd0, const float* __restrict__ Xd1,
    const __nv_bfloat16* __restrict__ WhL, const __nv_bfloat16* __restrict__ WlL,
    const float* __restrict__ biasg, const float* __restrict__ biasd,
    float* __restrict__ outg, float* __restrict__ outd, int gb) {
    extern __shared__ __nv_bfloat16 smem[];
    __nv_bfloat16* Ah = smem;
    __nv_bfloat16* Al = smem + SM_MAT;
    __nv_bfloat16* Bh = smem + 2 * SM_MAT;
    __nv_bfloat16* Bl = smem + 3 * SM_MAT;

    int tid = threadIdx.x;
    int wid = tid >> 5;
    int lane = tid & 31;

    bool gene = (int)blockIdx.x < gb;
    int m0, n, nterms;
    const float* Xa[3];
    const __nv_bfloat16* Bha[3];
    const __nv_bfloat16* Bla[3];
    const float* bias;
    float* out;
    if (gene) {
        m0 = blockIdx.x * 128; n = NG; nterms = 3;
        Xa[0] = Xg0; Xa[1] = Xg1; Xa[2] = Xg2;
        Bha[0] = WhL; Bha[1] = WhL + MM; Bha[2] = WhL + 2 * MM;
        Bla[0] = WlL; Bla[1] = WlL + MM; Bla[2] = WlL + 2 * MM;
        bias = biasg; out = outg;
    } else {
        m0 = (blockIdx.x - gb) * 128; n = ND; nterms = 2;
        Xa[0] = Xd0; Xa[1] = Xd1; Xa[2] = Xd0;
        Bha[0] = WhL + 3 * MM; Bha[1] = WhL + 4 * MM; Bha[2] = WhL + 3 * MM;
        Bla[0] = WlL + 3 * MM; Bla[1] = WlL + 4 * MM; Bla[2] = WlL + 3 * MM;
        bias = biasd; out = outd;
    }

    int arow = tid >> 1;
    int akh = (tid & 1) * 64;
    int gma = m0 + arow;
    bool avalid = gma < n;

    int wr = (wid & 3) * 32;
    int wc = (wid >> 2) * 64;
    int g = lane >> 2;
    int tg = lane & 3;

    uint32_t sAh = (uint32_t)__cvta_generic_to_shared(Ah);
    uint32_t sAl = (uint32_t)__cvta_generic_to_shared(Al);
    uint32_t sBh = (uint32_t)__cvta_generic_to_shared(Bh);
    uint32_t sBl = (uint32_t)__cvta_generic_to_shared(Bl);
    uint32_t aoff[2];
#pragma unroll
    for (int mt = 0; mt < 2; ++mt) {
        int row = wr + mt * 16 + ((lane >> 3) & 1) * 8 + (lane & 7);
        int kc = (lane >> 4) * 8;
        aoff[mt] = (uint32_t)((row * LDA + kc) * 2);
    }
    uint32_t boff[4];
#pragma unroll
    for (int m = 0; m < 4; ++m) {
        int nn = wc + m * 16 + ((lane >> 4) & 1) * 8 + (lane & 7);
        int kc = ((lane >> 3) & 1) * 8;
        boff[m] = (uint32_t)((nn * LDA + kc) * 2);
    }

    float acc[2][8][4];
#pragma unroll
    for (int mt = 0; mt < 2; ++mt)
#pragma unroll
        for (int nt = 0; nt < 8; ++nt)
#pragma unroll
            for (int q = 0; q < 4; ++q) acc[mt][nt][q] = 0.f;

    for (int t = 0; t < nterms; ++t) {
        __syncthreads();
        {   // A tile: fp32 -> bf16 hi/lo
            const float* X = Xa[t];
            const float* xrow = X + (size_t)gma * 128 + akh;
            int base = arow * LDA + akh;
#pragma unroll
            for (int c = 0; c < 8; ++c) {
                float4 v0 = make_float4(0.f, 0.f, 0.f, 0.f), v1 = v0;
                if (avalid) {
                    v0 = *(const float4*)(xrow + c * 8);
                    v1 = *(const float4*)(xrow + c * 8 + 4);
                }
                __nv_bfloat162 h0 = __floats2bfloat162_rn(v0.x, v0.y);
                __nv_bfloat162 h1 = __floats2bfloat162_rn(v0.z, v0.w);
                __nv_bfloat162 h2 = __floats2bfloat162_rn(v1.x, v1.y);
                __nv_bfloat162 h3 = __floats2bfloat162_rn(v1.z, v1.w);
                float2 f0 = __bfloat1622float2(h0), f1 = __bfloat1622float2(h1);
                float2 f2 = __bfloat1622float2(h2), f3 = __bfloat1622float2(h3);
                __nv_bfloat162 l0 = __floats2bfloat162_rn(v0.x - f0.x, v0.y - f0.y);
                __nv_bfloat162 l1 = __floats2bfloat162_rn(v0.z - f1.x, v0.w - f1.y);
                __nv_bfloat162 l2 = __floats2bfloat162_rn(v1.x - f2.x, v1.y - f2.y);
                __nv_bfloat162 l3 = __floats2bfloat162_rn(v1.z - f3.x, v1.w - f3.y);
                uint4 hv, lv;
                hv.x = *(uint32_t*)&h0; hv.y = *(uint32_t*)&h1;
                hv.z = *(uint32_t*)&h2; hv.w = *(uint32_t*)&h3;
                lv.x = *(uint32_t*)&l0; lv.y = *(uint32_t*)&l1;
                lv.z = *(uint32_t*)&l2; lv.w = *(uint32_t*)&l3;
                *(uint4*)&Ah[base + c * 8] = hv;
                *(uint4*)&Al[base + c * 8] = lv;
            }
        }
        {   // B tile copy
            const __nv_bfloat16* bh = Bha[t];
            const __nv_bfloat16* bl = Bla[t];
#pragma unroll
            for (int c = 0; c < 8; ++c) {
                int chunk = c * 256 + tid;
                int row = chunk >> 4;
                int k0 = (chunk & 15) * 8;
                int d = row * LDA + k0;
                *(uint4*)&Bh[d] = *(const uint4*)(bh + (size_t)chunk * 8);
                *(uint4*)&Bl[d] = *(const uint4*)(bl + (size_t)chunk * 8);
            }
        }
        __syncthreads();
#pragma unroll
        for (int ks = 0; ks < 8; ++ks) {
            uint32_t kb2 = (uint32_t)(ks * 32);
            uint32_t ah[2][4], al[2][4], bh[4][4], bl[4][4];
            ldm_x4(ah[0], sAh + aoff[0] + kb2);
            ldm_x4(ah[1], sAh + aoff[1] + kb2);
            ldm_x4(al[0], sAl + aoff[0] + kb2);
            ldm_x4(al[1], sAl + aoff[1] + kb2);
#pragma unroll
            for (int m = 0; m < 4; ++m) {
                ldm_x4(bh[m], sBh + boff[m] + kb2);
                ldm_x4(bl[m], sBl + boff[m] + kb2);
            }
#pragma unroll
            for (int mt = 0; mt < 2; ++mt)
#pragma unroll
                for (int m = 0; m < 4; ++m) {
                    mma_bf16(acc[mt][2 * m], ah[mt], bh[m][0], bh[m][1]);
                    mma_bf16(acc[mt][2 * m], ah[mt], bl[m][0], bl[m][1]);
                    mma_bf16(acc[mt][2 * m], al[mt], bh[m][0], bh[m][1]);
                    mma_bf16(acc[mt][2 * m + 1], ah[mt], bh[m][2], bh[m][3]);
                    mma_bf16(acc[mt][2 * m + 1], ah[mt], bl[m][2], bl[m][3]);
                    mma_bf16(acc[mt][2 * m + 1], al[mt], bh[m][2], bh[m][3]);
                }
        }
    }

#pragma unroll
    for (int mt = 0; mt < 2; ++mt) {
        int r0v = m0 + wr + mt * 16 + g;
        int r1v = r0v + 8;
#pragma unroll
        for (int nt = 0; nt < 8; ++nt) {
            int col = wc + nt * 8 + tg * 2;
            float b0 = __ldg(&bias[col]);
            float b1 = __ldg(&bias[col + 1]);
            if (r0v < n) {
                float2 o = make_float2(acc[mt][nt][0] + b0, acc[mt][nt][1] + b1);
                *(float2*)&out[(size_t)r0v * 128 + col] = o;
            }
            if (r1v < n) {
                float2 o = make_float2(acc[mt][nt][2] + b0, acc[mt][nt][3] + b1);
                *(float2*)&out[(size_t)r1v * 128 + col] = o;
            }
        }
    }
}

// ---------------- bias combine ----------------
__global__ void bias_combine_kernel(const float* __restrict__ bd1, const float* __restrict__ bs1,
                                    const float* __restrict__ bu1, const float* __restrict__ Wu1,
                                    const float* __restrict__ bd2, const float* __restrict__ bs2,
                                    const float* __restrict__ bu2, const float* __restrict__ Wu2) {
    int layer = blockIdx.x >> 1;
    int which = blockIdx.x & 1;
    int h = threadIdx.x;
    const float* bd = layer ? bd2 : bd1;
    const float* bs = layer ? bs2 : bs1;
    const float* bu = layer ? bu2 : bu1;
    const float* Wu = layer ? Wu2 : Wu1;
    auto cfun = [&](int i) {
        float s = bu[i * 128 + h];
        const float* wt = Wu + (size_t)i * WU;
        for (int k = 0; k < 128; ++k) s = fmaf(bd[i * 128 + k], wt[k * 128 + h], s);
        const float* wb = wt + WUB;
        for (int k = 0; k < 128; ++k) s = fmaf(bs[i * 128 + k], wb[k * 128 + h], s);
        return s;
    };
    if (which == 0)
        d_bg[layer][h] = 0.5f * (cfun(0) + cfun(2));
    else
        d_bd[layer][h] = cfun(1);
}

// ---------------- batch norm ----------------
__global__ void bn_stats_kernel(const float* __restrict__ xg, const float* __restrict__ xd, int gb) {
    int c = threadIdx.x;
    bool gene = (int)blockIdx.x < gb;
    const float* x = gene ? xg : xd;
    int nn = gene ? NG : ND;
    int b = gene ? blockIdx.x : (blockIdx.x - gb);
    int r0 = b * 128;
    int rend = min(r0 + 128, nn);
    float s = 0.f, s2 = 0.f;
    for (int r = r0; r < rend; ++r) {
        float v = x[(size_t)r * 128 + c];
        s += v;
        s2 = fmaf(v, v, s2);
    }
    int off = gene ? 0 : 128;
    atomicAdd(&d_bn_acc[off + c], s);
    atomicAdd(&d_bn_acc[256 + off + c], s2);
}
__global__ void bn_final_kernel(const float* __restrict__ gamma, const float* __restrict__ beta) {
    int idx = blockIdx.x;
    int c = threadIdx.x;
    float nn = (idx == 0) ? (float)NG : (float)ND;
    float mean = d_bn_acc[idx * 128 + c] / nn;
    float var = d_bn_acc[256 + idx * 128 + c] / nn - mean * mean;
    float sc = gamma[idx * 128 + c] * rsqrtf(var + 1e-5f);
    d_bn_scale[idx][c] = sc;
    d_bn_shift[idx][c] = beta[idx * 128 + c] - mean * sc;
}
// apply BN + leaky relu; also emit bf16 shadow for the layer-2 gather
__global__ void bn_apply_kernel(float* __restrict__ xg, float* __restrict__ xd) {
    int i = blockIdx.x * blockDim.x + threadIdx.x;
    int which;
    float* x;
    __nv_bfloat16* o;
    if (i < NG * 32) { which = 0; x = xg; o = d_xbf_g; }
    else if (i < (NG + ND) * 32) { which = 1; x = xd; o = d_xbf_d; i -= NG * 32; }
    else return;
    int q = i & 31;
    int c = q * 4;
    const float* sc = d_bn_scale[which];
    const float* sh = d_bn_shift[which];
    float4 v = *(float4*)&x[(size_t)i * 4];
    v.x = fmaf(v.x, sc[c + 0], sh[c + 0]);
    v.y = fmaf(v.y, sc[c + 1], sh[c + 1]);
    v.z = fmaf(v.z, sc[c + 2], sh[c + 2]);
    v.w = fmaf(v.w, sc[c + 3], sh[c + 3]);
    v.x = v.x >= 0.f ? v.x : 0.01f * v.x;
    v.y = v.y >= 0.f ? v.y : 0.01f * v.y;
    v.z = v.z >= 0.f ? v.z : 0.01f * v.z;
    v.w = v.w >= 0.f ? v.w : 0.01f * v.w;
    *(float4*)&x[(size_t)i * 4] = v;
    __nv_bfloat162 a = __floats2bfloat162_rn(v.x, v.y);
    __nv_bfloat162 b = __floats2bfloat162_rn(v.z, v.w);
    uint2 u;
    u.x = *(uint32_t*)&a;
    u.y = *(uint32_t*)&b;
    *(uint2*)&o[(size_t)i * 4] = u;
}

// ---------------- decoder ----------------
__global__ void decode_kernel(const int* __restrict__ ls, const int* __restrict__ ld,
                              float* __restrict__ out) {
    int gw = (blockIdx.x * blockDim.x + threadIdx.x) >> 5;
    int lane = threadIdx.x & 31;
    if (gw >= ELAB) return;
    int a = __ldg(&ls[gw]);
    int b = __ldg(&ld[gw]);
    float4 u = *(const float4*)&d_g2[(size_t)a * 128 + lane * 4];
    float4 v = *(const float4*)&d_d2[(size_t)b * 128 + lane * 4];
    float s = u.x * v.x + u.y * v.y + u.z * v.z + u.w * v.w;
#pragma unroll
    for (int o = 16; o; o >>= 1) s += __shfl_xor_sync(0xFFFFFFFFu, s, o);
    if (lane == 0) out[gw] = s;
}

// ---------------- launch ----------------
static inline int cdiv(int a, int b) { return (a + b - 1) / b; }

extern "C" void kernel_launch(void* const* d_in, const int* in_sizes, int n_in,
                              void* d_out, int out_size) {
    const float* x_gene = (const float*)d_in[0];
    const float* x_dis  = (const float*)d_in[1];
    const float* W_dst1 = (const float*)d_in[2];
    const float* W_src1 = (const float*)d_in[3];
    const float* W_upd1 = (const float*)d_in[4];
    const float* b_dst1 = (const float*)d_in[5];
    const float* b_src1 = (const float*)d_in[6];
    const float* b_upd1 = (const float*)d_in[7];
    const float* W_dst2 = (const float*)d_in[8];
    const float* W_src2 = (const float*)d_in[9];
    const float* W_upd2 = (const float*)d_in[10];
    const float* b_dst2 = (const float*)d_in[11];
    const float* b_src2 = (const float*)d_in[12];
    const float* b_upd2 = (const float*)d_in[13];
    const float* bn_gamma = (const float*)d_in[14];
    const float* bn_beta  = (const float*)d_in[15];
    const int* gg_src  = (const int*)d_in[16];
    const int* gg_dst  = (const int*)d_in[17];
    const int* gda_src = (const int*)d_in[18];
    const int* gda_dst = (const int*)d_in[19];
    const int* label_src = (const int*)d_in[20];
    const int* label_dst = (const int*)d_in[21];
    float* out = (float*)d_out;

    static bool attr_set = false;
    if (!attr_set) {
        cudaFuncSetAttribute(mmagemm_kernel, cudaFuncAttributeMaxDynamicSharedMemorySize, SMEM_TOTAL);
        attr_set = true;
    }

    float *agg_gg, *agg_rev, *agg_d, *g1, *d1, *g2, *d2, *bg, *bd;
    __nv_bfloat16 *Wh, *Wl, *xbg, *xbd;
    cudaGetSymbolAddress((void**)&agg_gg, d_agg_gg);
    cudaGetSymbolAddress((void**)&agg_rev, d_agg_rev);
    cudaGetSymbolAddress((void**)&agg_d, d_agg_d);
    cudaGetSymbolAddress((void**)&g1, d_g1);
    cudaGetSymbolAddress((void**)&d1, d_d1);
    cudaGetSymbolAddress((void**)&g2, d_g2);
    cudaGetSymbolAddress((void**)&d2, d_d2);
    cudaGetSymbolAddress((void**)&Wh, d_Wh);
    cudaGetSymbolAddress((void**)&Wl, d_Wl);
    cudaGetSymbolAddress((void**)&bg, d_bg);
    cudaGetSymbolAddress((void**)&bd, d_bd);
    cudaGetSymbolAddress((void**)&xbg, d_xbf_g);
    cudaGetSymbolAddress((void**)&xbd, d_xbf_d);

    const int GB = cdiv(NG, 128), DB = cdiv(ND, 128);

    // CSR build
    init_kernel<<<cdiv(NTOT + 512, 256), 256>>>();
    deg_all_kernel<<<cdiv(ETOT, 256), 256>>>(gg_dst, gda_dst, gda_src);
    scan_all_kernel<<<3, 1024>>>();
    fill_all_kernel<<<cdiv(ETOT, 256), 256>>>(gg_src, gg_dst, gda_src, gda_dst);

    // bf16 shadow of layer-1 inputs
    tobf16_kernel<<<cdiv((NG + ND) * 32, 256), 256>>>(x_gene, x_dis);

    // layer-1 aggregation (bf16 reads)
    gather_all_kernel<<<cdiv(NTOT * 32, 256), 256>>>(xbg, xbd);

    // weight prep
    wprep_kernel<<<10, 256>>>(W_dst1, W_src1, W_upd1, W_dst2, W_src2, W_upd2, Wh, Wl);
    bias_combine_kernel<<<4, 128>>>(b_dst1, b_src1, b_upd1, W_upd1,
                                    b_dst2, b_src2, b_upd2, W_upd2);

    // layer-1 GEMMs
    mmagemm_kernel<<<GB + DB, 256, SMEM_TOTAL>>>(
        x_gene, agg_gg, agg_rev, x_dis, agg_d,
        Wh, Wl, bg, bd, g1, d1, GB);

    // BN + leaky relu (apply also writes bf16 shadows)
    bn_stats_kernel<<<GB + DB, 128>>>(g1, d1, GB);
    bn_final_kernel<<<2, 128>>>(bn_gamma, bn_beta);
    bn_apply_kernel<<<cdiv((NG + ND) * 32, 256), 256>>>(g1, d1);

    // layer-2 aggregation (bf16 reads)
    gather_all_kernel<<<cdiv(NTOT * 32, 256), 256>>>(xbg, xbd);

    // layer-2 GEMMs
    mmagemm_kernel<<<GB + DB, 256, SMEM_TOTAL>>>(
        g1, agg_gg, agg_rev, d1, agg_d,
        Wh + 5 * MM, Wl + 5 * MM, bg + HD, bd + HD, g2, d2, GB);

    // decoder
    decode_kernel<<<cdiv(ELAB * 32, 256), 256>>>(label_src, label_dst, out);
}

// round 8
// speedup vs baseline: 2.4158x; 1.0594x over previous
#include <cuda_runtime.h>
#include <cuda_bf16.h>
#include <cstdint>
#include <cstddef>

#define NG 50000
#define ND 20000
#define HD 128
#define EGG 800000
#define EGDA 400000
#define ELAB 200000
#define ETOT (EGG + 2 * EGDA)
#define NTOT (NG + ND + NG)
#define MM 16384
#define WU 32768
#define WUB 16384
#define NGP 50048   // padded to 128-row tiles (391*128)
#define NDP 20096   // 157*128

// ---------------- scratch ----------------
// bf16 hi/lo planes (A-inputs for GEMM + gather tables), padded
__device__ __nv_bfloat16 d_xg_h[(size_t)NGP * HD];
__device__ __nv_bfloat16 d_xg_l[(size_t)NGP * HD];
__device__ __nv_bfloat16 d_xd_h[(size_t)NDP * HD];
__device__ __nv_bfloat16 d_xd_l[(size_t)NDP * HD];
__device__ __nv_bfloat16 d_agg_gg_h[(size_t)NGP * HD];
__device__ __nv_bfloat16 d_agg_gg_l[(size_t)NGP * HD];
__device__ __nv_bfloat16 d_agg_rev_h[(size_t)NGP * HD];
__device__ __nv_bfloat16 d_agg_rev_l[(size_t)NGP * HD];
__device__ __nv_bfloat16 d_agg_d_h[(size_t)NDP * HD];
__device__ __nv_bfloat16 d_agg_d_l[(size_t)NDP * HD];
// fp32 GEMM outputs
__device__ float d_g1[(size_t)NG * HD];
__device__ float d_d1[(size_t)ND * HD];
__device__ float d_g2[(size_t)NG * HD];
__device__ float d_d2[(size_t)ND * HD];
__device__ float d_rdeg_gg[NG];
__device__ float d_rdeg_rev[NG];
__device__ float d_rdeg_d[ND];
__device__ int d_ideg[NTOT];
__device__ int d_ptr_gg[NG + 1];
__device__ int d_ptr_d[ND + 1];
__device__ int d_ptr_rev[NG + 1];
__device__ int d_cur_gg[NG];
__device__ int d_cur_d[ND];
__device__ int d_cur_rev[NG];
__device__ int d_idx_gg[EGG];
__device__ int d_idx_d[EGDA];
__device__ int d_idx_rev[EGDA];
__device__ __nv_bfloat16 d_Wh[10 * MM];
__device__ __nv_bfloat16 d_Wl[10 * MM];
__device__ float d_bg[2][HD];
__device__ float d_bd[2][HD];
__device__ float d_bn_acc[512];
__device__ float d_bn_scale[2][HD];
__device__ float d_bn_shift[2][HD];

// split fp32 into bf16 hi/lo pair (packed bf16x2 per 2 elems)
__device__ __forceinline__ void split2(float x, float y, uint32_t& h, uint32_t& l) {
    __nv_bfloat162 hb = __floats2bfloat162_rn(x, y);
    float2 f = __bfloat1622float2(hb);
    __nv_bfloat162 lb = __floats2bfloat162_rn(x - f.x, y - f.y);
    h = *(uint32_t*)&hb;
    l = *(uint32_t*)&lb;
}

// ---------------- CSR build ----------------
__global__ void init_kernel() {
    int i = blockIdx.x * blockDim.x + threadIdx.x;
    if (i < NTOT) d_ideg[i] = 0;
    else if (i < NTOT + 512) d_bn_acc[i - NTOT] = 0.f;
}

__global__ void deg_all_kernel(const int* __restrict__ gg_dst, const int* __restrict__ gda_dst,
                               const int* __restrict__ gda_src) {
    int i = blockIdx.x * blockDim.x + threadIdx.x;
    if (i < EGG) {
        atomicAdd(&d_ideg[__ldg(&gg_dst[i])], 1);
    } else if (i < EGG + EGDA) {
        atomicAdd(&d_ideg[NG + __ldg(&gda_dst[i - EGG])], 1);
    } else if (i < ETOT) {
        atomicAdd(&d_ideg[NG + ND + __ldg(&gda_src[i - EGG - EGDA])], 1);
    }
}

__global__ void scan_all_kernel() {
    __shared__ int sm[1024];
    int rel = blockIdx.x;
    const int* deg;
    int n;
    int* ptr;
    int* cur;
    float* rdeg;
    if (rel == 0) { deg = d_ideg; n = NG; ptr = d_ptr_gg; cur = d_cur_gg; rdeg = d_rdeg_gg; }
    else if (rel == 1) { deg = d_ideg + NG; n = ND; ptr = d_ptr_d; cur = d_cur_d; rdeg = d_rdeg_d; }
    else { deg = d_ideg + NG + ND; n = NG; ptr = d_ptr_rev; cur = d_cur_rev; rdeg = d_rdeg_rev; }
    int tid = threadIdx.x;
    int chunk = (n + 1023) >> 10;
    int lo = tid * chunk;
    int hi = min(lo + chunk, n);
    int s = 0;
    for (int i = lo; i < hi; ++i) s += deg[i];
    sm[tid] = s;
    __syncthreads();
    for (int off = 1; off < 1024; off <<= 1) {
        int v = 0;
        if (tid >= off) v = sm[tid - off];
        __syncthreads();
        sm[tid] += v;
        __syncthreads();
    }
    int run = sm[tid] - s;
    for (int i = lo; i < hi; ++i) {
        int dg = deg[i];
        ptr[i] = run;
        cur[i] = run;
        rdeg[i] = 1.0f / fmaxf((float)dg, 1.0f);
        run += dg;
    }
    if (tid == 1023) ptr[n] = sm[1023];
}

__global__ void fill_all_kernel(const int* __restrict__ gg_src, const int* __restrict__ gg_dst,
                                const int* __restrict__ gda_src, const int* __restrict__ gda_dst) {
    int i = blockIdx.x * blockDim.x + threadIdx.x;
    if (i < EGG) {
        int p = atomicAdd(&d_cur_gg[__ldg(&gg_dst[i])], 1);
        d_idx_gg[p] = __ldg(&gg_src[i]);
    } else if (i < EGG + EGDA) {
        int e = i - EGG;
        int p = atomicAdd(&d_cur_d[__ldg(&gda_dst[e])], 1);
        d_idx_d[p] = __ldg(&gda_src[e]);
    } else if (i < ETOT) {
        int e = i - EGG - EGDA;
        int p = atomicAdd(&d_cur_rev[__ldg(&gda_src[e])], 1);
        d_idx_rev[p] = __ldg(&gda_dst[e]);
    }
}

// ---------------- fp32 -> hi/lo shadow (layer-1 inputs) ----------------
__global__ void tobf16_kernel(const float* __restrict__ xg, const float* __restrict__ xd) {
    int i = blockIdx.x * blockDim.x + threadIdx.x;  // 4-elem chunks
    const float* x;
    __nv_bfloat16 *oh, *ol;
    if (i < NG * 32) { x = xg; oh = d_xg_h; ol = d_xg_l; }
    else if (i < (NG + ND) * 32) { x = xd; oh = d_xd_h; ol = d_xd_l; i -= NG * 32; }
    else return;
    float4 v = *(const float4*)&x[(size_t)i * 4];
    uint2 uh, ul;
    split2(v.x, v.y, uh.x, ul.x);
    split2(v.z, v.w, uh.y, ul.y);
    *(uint2*)&oh[(size_t)i * 4] = uh;
    *(uint2*)&ol[(size_t)i * 4] = ul;
}

// ---------------- fused gather: reads hi/lo planes, writes hi/lo agg planes ----------------
__global__ __launch_bounds__(256) void gather_all_kernel() {
    int w = (blockIdx.x * blockDim.x + threadIdx.x) >> 5;
    int lane = threadIdx.x & 31;
    const __nv_bfloat16 *Xh, *Xl;
    const int* ptr;
    const int* idx;
    const float* rdeg;
    __nv_bfloat16 *Oh, *Ol;
    int r;
    if (w < NG) {
        Xh = d_xg_h; Xl = d_xg_l; ptr = d_ptr_gg; idx = d_idx_gg; rdeg = d_rdeg_gg;
        Oh = d_agg_gg_h; Ol = d_agg_gg_l; r = w;
    } else if (w < NG + ND) {
        Xh = d_xg_h; Xl = d_xg_l; ptr = d_ptr_d; idx = d_idx_d; rdeg = d_rdeg_d;
        Oh = d_agg_d_h; Ol = d_agg_d_l; r = w - NG;
    } else if (w < NTOT) {
        Xh = d_xd_h; Xl = d_xd_l; ptr = d_ptr_rev; idx = d_idx_rev; rdeg = d_rdeg_rev;
        Oh = d_agg_rev_h; Ol = d_agg_rev_l; r = w - NG - ND;
    } else return;
    int s = __ldg(&ptr[r]);
    int e = __ldg(&ptr[r + 1]);
    float4 a0 = make_float4(0.f, 0.f, 0.f, 0.f);
    float4 a1 = a0, a2 = a0, a3 = a0;
    int j = s;
    for (; j + 3 < e; j += 4) {
        size_t b0 = (size_t)__ldg(&idx[j]) * HD + lane * 4;
        size_t b1 = (size_t)__ldg(&idx[j + 1]) * HD + lane * 4;
        size_t b2 = (size_t)__ldg(&idx[j + 2]) * HD + lane * 4;
        size_t b3 = (size_t)__ldg(&idx[j + 3]) * HD + lane * 4;
        uint2 h0 = *(const uint2*)&Xh[b0], l0 = *(const uint2*)&Xl[b0];
        uint2 h1 = *(const uint2*)&Xh[b1], l1 = *(const uint2*)&Xl[b1];
        uint2 h2 = *(const uint2*)&Xh[b2], l2 = *(const uint2*)&Xl[b2];
        uint2 h3 = *(const uint2*)&Xh[b3], l3 = *(const uint2*)&Xl[b3];
        float2 p, q;
        p = __bfloat1622float2(*(__nv_bfloat162*)&h0.x); q = __bfloat1622float2(*(__nv_bfloat162*)&l0.x);
        a0.x += p.x + q.x; a0.y += p.y + q.y;
        p = __bfloat1622float2(*(__nv_bfloat162*)&h0.y); q = __bfloat1622float2(*(__nv_bfloat162*)&l0.y);
        a0.z += p.x + q.x; a0.w += p.y + q.y;
        p = __bfloat1622float2(*(__nv_bfloat162*)&h1.x); q = __bfloat1622float2(*(__nv_bfloat162*)&l1.x);
        a1.x += p.x + q.x; a1.y += p.y + q.y;
        p = __bfloat1622float2(*(__nv_bfloat162*)&h1.y); q = __bfloat1622float2(*(__nv_bfloat162*)&l1.y);
        a1.z += p.x + q.x; a1.w += p.y + q.y;
        p = __bfloat1622float2(*(__nv_bfloat162*)&h2.x); q = __bfloat1622float2(*(__nv_bfloat162*)&l2.x);
        a2.x += p.x + q.x; a2.y += p.y + q.y;
        p = __bfloat1622float2(*(__nv_bfloat162*)&h2.y); q = __bfloat1622float2(*(__nv_bfloat162*)&l2.y);
        a2.z += p.x + q.x; a2.w += p.y + q.y;
        p = __bfloat1622float2(*(__nv_bfloat162*)&h3.x); q = __bfloat1622float2(*(__nv_bfloat162*)&l3.x);
        a3.x += p.x + q.x; a3.y += p.y + q.y;
        p = __bfloat1622float2(*(__nv_bfloat162*)&h3.y); q = __bfloat1622float2(*(__nv_bfloat162*)&l3.y);
        a3.z += p.x + q.x; a3.w += p.y + q.y;
    }
    for (; j < e; ++j) {
        size_t b0 = (size_t)__ldg(&idx[j]) * HD + lane * 4;
        uint2 h0 = *(const uint2*)&Xh[b0], l0 = *(const uint2*)&Xl[b0];
        float2 p, q;
        p = __bfloat1622float2(*(__nv_bfloat162*)&h0.x); q = __bfloat1622float2(*(__nv_bfloat162*)&l0.x);
        a0.x += p.x + q.x; a0.y += p.y + q.y;
        p = __bfloat1622float2(*(__nv_bfloat162*)&h0.y); q = __bfloat1622float2(*(__nv_bfloat162*)&l0.y);
        a0.z += p.x + q.x; a0.w += p.y + q.y;
    }
    float rr = __ldg(&rdeg[r]);
    float ox = (a0.x + a1.x + a2.x + a3.x) * rr;
    float oy = (a0.y + a1.y + a2.y + a3.y) * rr;
    float oz = (a0.z + a1.z + a2.z + a3.z) * rr;
    float ow = (a0.w + a1.w + a2.w + a3.w) * rr;
    uint2 uh, ul;
    split2(ox, oy, uh.x, ul.x);
    split2(oz, ow, uh.y, ul.y);
    size_t ob = (size_t)r * HD + lane * 4;
    *(uint2*)&Oh[ob] = uh;
    *(uint2*)&Ol[ob] = ul;
}

// ---------------- fused weight prep ----------------
__global__ __launch_bounds__(256) void wprep_kernel(
    const float* __restrict__ Wd1, const float* __restrict__ Ws1, const float* __restrict__ Wu1,
    const float* __restrict__ Wd2, const float* __restrict__ Ws2, const float* __restrict__ Wu2,
    __nv_bfloat16* __restrict__ Wh, __nv_bfloat16* __restrict__ Wl) {
    __shared__ __align__(16) float Xs[16][132];
    __shared__ __align__(16) float Ws_[16][128];
    int mtx = blockIdx.x;
    int l = mtx / 5, j = mtx % 5;
    const float* Wdl = l ? Wd2 : Wd1;
    const float* Wsl = l ? Ws2 : Ws1;
    const float* Wul = l ? Wu2 : Wu1;
    const float* X0 = nullptr;
    const float* W0 = nullptr;
    const float* X1 = nullptr;
    const float* W1 = nullptr;
    float scale = 1.f;
    switch (j) {
        case 0: X0 = Wdl; W0 = Wul; X1 = Wdl + 2 * MM; W1 = Wul + 2 * WU; scale = 0.5f; break;
        case 1: X0 = Wsl; W0 = Wul + WUB; scale = 0.5f; break;
        case 2: X0 = Wsl + 2 * MM; W0 = Wul + 2 * WU + WUB; scale = 0.5f; break;
        case 3: X0 = Wdl + MM; W0 = Wul + WU; scale = 1.f; break;
        case 4: X0 = Wsl + MM; W0 = Wul + WU + WUB; scale = 1.f; break;
    }
    int tid = threadIdx.x;
    float acc[8][8];
#pragma unroll
    for (int i = 0; i < 8; ++i)
#pragma unroll
        for (int q = 0; q < 8; ++q) acc[i][q] = 0.f;
    const float* Xp[2] = {X0, X1};
    const float* Wp[2] = {W0, W1};
    int rA = tid >> 2, kq = tid & 3, krow = tid >> 4, cq = tid & 15;
    int tx = tid & 15, ty = tid >> 4;
    for (int t = 0; t < 2; ++t) {
        const float* X = Xp[t];
        if (!X) continue;
        const float* W = Wp[t];
        for (int kc = 0; kc < 8; ++kc) {
#pragma unroll
            for (int h = 0; h < 2; ++h) {
                int r = rA + h * 64;
                float4 v = *(const float4*)&X[(size_t)r * 128 + kc * 16 + kq * 4];
                Xs[kq * 4 + 0][r] = v.x;
                Xs[kq * 4 + 1][r] = v.y;
                Xs[kq * 4 + 2][r] = v.z;
                Xs[kq * 4 + 3][r] = v.w;
            }
#pragma unroll
            for (int h = 0; h < 2; ++h) {
                int c = cq + h * 16;
                *(float4*)&Ws_[krow][c * 4] = *(const float4*)&W[(size_t)(kc * 16 + krow) * 128 + c * 4];
            }
            __syncthreads();
#pragma unroll
            for (int k = 0; k < 16; ++k) {
                float a[8], b[8];
                *(float4*)&a[0] = *(const float4*)&Xs[k][ty * 8];
                *(float4*)&a[4] = *(const float4*)&Xs[k][ty * 8 + 4];
                *(float4*)&b[0] = *(const float4*)&Ws_[k][tx * 8];
                *(float4*)&b[4] = *(const float4*)&Ws_[k][tx * 8 + 4];
#pragma unroll
                for (int i = 0; i < 8; ++i)
#pragma unroll
                    for (int q = 0; q < 8; ++q) acc[i][q] = fmaf(a[i], b[q], acc[i][q]);
            }
            __syncthreads();
        }
    }
    __nv_bfloat16* oh = Wh + (size_t)mtx * MM;
    __nv_bfloat16* ol = Wl + (size_t)mtx * MM;
#pragma unroll
    for (int i = 0; i < 8; ++i) {
        int krow2 = ty * 8 + i;
#pragma unroll
        for (int q = 0; q < 8; ++q) {
            int col = tx * 8 + q;
            float v = acc[i][q] * scale;
            __nv_bfloat16 h = __float2bfloat16(v);
            oh[col * 128 + krow2] = h;
            ol[col * 128 + krow2] = __float2bfloat16(v - __bfloat162float(h));
        }
    }
}

// ---------------- mma.sync node GEMM (A/B both precomputed bf16 hi/lo planes) ----------------
#define LDA 136
#define SM_MAT (128 * LDA)
#define SMEM_TOTAL (4 * SM_MAT * 2)

__device__ __forceinline__ void mma_bf16(float* c, const uint32_t* a, uint32_t b0, uint32_t b1) {
    asm volatile(
        "mma.sync.aligned.m16n8k16.row.col.f32.bf16.bf16.f32 "
        "{%0,%1,%2,%3}, {%4,%5,%6,%7}, {%8,%9}, {%0,%1,%2,%3};"
        : "+f"(c[0]), "+f"(c[1]), "+f"(c[2]), "+f"(c[3])
        : "r"(a[0]), "r"(a[1]), "r"(a[2]), "r"(a[3]), "r"(b0), "r"(b1));
}
__device__ __forceinline__ void ldm_x4(uint32_t* r, uint32_t saddr) {
    asm volatile("ldmatrix.sync.aligned.m8n8.x4.shared.b16 {%0,%1,%2,%3}, [%4];"
                 : "=r"(r[0]), "=r"(r[1]), "=r"(r[2]), "=r"(r[3]) : "r"(saddr));
}

__global__ __launch_bounds__(256, 1) void mmagemm_kernel(
    const __nv_bfloat16* __restrict__ WhL, const __nv_bfloat16* __restrict__ WlL,
    const float* __restrict__ biasg, const float* __restrict__ biasd,
    float* __restrict__ outg, float* __restrict__ outd, int gb) {
    extern __shared__ __nv_bfloat16 smem[];
    __nv_bfloat16* Ah = smem;
    __nv_bfloat16* Al = smem + SM_MAT;
    __nv_bfloat16* Bh = smem + 2 * SM_MAT;
    __nv_bfloat16* Bl = smem + 3 * SM_MAT;

    int tid = threadIdx.x;
    int wid = tid >> 5;
    int lane = tid & 31;

    bool gene = (int)blockIdx.x < gb;
    int m0, n, nterms;
    const __nv_bfloat16* AHa[3];
    const __nv_bfloat16* ALa[3];
    const __nv_bfloat16* Bha[3];
    const __nv_bfloat16* Bla[3];
    const float* bias;
    float* out;
    if (gene) {
        m0 = blockIdx.x * 128; n = NG; nterms = 3;
        AHa[0] = d_xg_h; ALa[0] = d_xg_l;
        AHa[1] = d_agg_gg_h; ALa[1] = d_agg_gg_l;
        AHa[2] = d_agg_rev_h; ALa[2] = d_agg_rev_l;
        Bha[0] = WhL; Bha[1] = WhL + MM; Bha[2] = WhL + 2 * MM;
        Bla[0] = WlL; Bla[1] = WlL + MM; Bla[2] = WlL + 2 * MM;
        bias = biasg; out = outg;
    } else {
        m0 = (blockIdx.x - gb) * 128; n = ND; nterms = 2;
        AHa[0] = d_xd_h; ALa[0] = d_xd_l;
        AHa[1] = d_agg_d_h; ALa[1] = d_agg_d_l;
        AHa[2] = d_xd_h; ALa[2] = d_xd_l;
        Bha[0] = WhL + 3 * MM; Bha[1] = WhL + 4 * MM; Bha[2] = WhL + 3 * MM;
        Bla[0] = WlL + 3 * MM; Bla[1] = WlL + 4 * MM; Bla[2] = WlL + 3 * MM;
        bias = biasd; out = outd;
    }

    int wr = (wid & 3) * 32;
    int wc = (wid >> 2) * 64;
    int g = lane >> 2;
    int tg = lane & 3;

    uint32_t sAh = (uint32_t)__cvta_generic_to_shared(Ah);
    uint32_t sAl = (uint32_t)__cvta_generic_to_shared(Al);
    uint32_t sBh = (uint32_t)__cvta_generic_to_shared(Bh);
    uint32_t sBl = (uint32_t)__cvta_generic_to_shared(Bl);
    uint32_t aoff[2];
#pragma unroll
    for (int mt = 0; mt < 2; ++mt) {
        int row = wr + mt * 16 + ((lane >> 3) & 1) * 8 + (lane & 7);
        int kc = (lane >> 4) * 8;
        aoff[mt] = (uint32_t)((row * LDA + kc) * 2);
    }
    uint32_t boff[4];
#pragma unroll
    for (int m = 0; m < 4; ++m) {
        int nn = wc + m * 16 + ((lane >> 4) & 1) * 8 + (lane & 7);
        int kc = ((lane >> 3) & 1) * 8;
        boff[m] = (uint32_t)((nn * LDA + kc) * 2);
    }

    float acc[2][8][4];
#pragma unroll
    for (int mt = 0; mt < 2; ++mt)
#pragma unroll
        for (int nt = 0; nt < 8; ++nt)
#pragma unroll
            for (int q = 0; q < 4; ++q) acc[mt][nt][q] = 0.f;

    for (int t = 0; t < nterms; ++t) {
        __syncthreads();
        {   // A + B tile copies (pure bf16 copies, padded sources — no guards)
            const __nv_bfloat16* ah = AHa[t];
            const __nv_bfloat16* al = ALa[t];
            const __nv_bfloat16* bh = Bha[t];
            const __nv_bfloat16* bl = Bla[t];
#pragma unroll
            for (int c = 0; c < 8; ++c) {
                int chunk = c * 256 + tid;
                int row = chunk >> 4;
                int k0 = (chunk & 15) * 8;
                int d = row * LDA + k0;
                size_t so = (size_t)(m0 + row) * 128 + k0;
                *(uint4*)&Ah[d] = *(const uint4*)(ah + so);
                *(uint4*)&Al[d] = *(const uint4*)(al + so);
                *(uint4*)&Bh[d] = *(const uint4*)(bh + (size_t)chunk * 8);
                *(uint4*)&Bl[d] = *(const uint4*)(bl + (size_t)chunk * 8);
            }
        }
        __syncthreads();
#pragma unroll
        for (int ks = 0; ks < 8; ++ks) {
            uint32_t kb2 = (uint32_t)(ks * 32);
            uint32_t ah[2][4], al[2][4], bh[4][4], bl[4][4];
            ldm_x4(ah[0], sAh + aoff[0] + kb2);
            ldm_x4(ah[1], sAh + aoff[1] + kb2);
            ldm_x4(al[0], sAl + aoff[0] + kb2);
            ldm_x4(al[1], sAl + aoff[1] + kb2);
#pragma unroll
            for (int m = 0; m < 4; ++m) {
                ldm_x4(bh[m], sBh + boff[m] + kb2);
                ldm_x4(bl[m], sBl + boff[m] + kb2);
            }
#pragma unroll
            for (int mt = 0; mt < 2; ++mt)
#pragma unroll
                for (int m = 0; m < 4; ++m) {
                    mma_bf16(acc[mt][2 * m], ah[mt], bh[m][0], bh[m][1]);
                    mma_bf16(acc[mt][2 * m], ah[mt], bl[m][0], bl[m][1]);
                    mma_bf16(acc[mt][2 * m], al[mt], bh[m][0], bh[m][1]);
                    mma_bf16(acc[mt][2 * m + 1], ah[mt], bh[m][2], bh[m][3]);
                    mma_bf16(acc[mt][2 * m + 1], ah[mt], bl[m][2], bl[m][3]);
                    mma_bf16(acc[mt][2 * m + 1], al[mt], bh[m][2], bh[m][3]);
                }
        }
    }

#pragma unroll
    for (int mt = 0; mt < 2; ++mt) {
        int r0v = m0 + wr + mt * 16 + g;
        int r1v = r0v + 8;
#pragma unroll
        for (int nt = 0; nt < 8; ++nt) {
            int col = wc + nt * 8 + tg * 2;
            float b0 = __ldg(&bias[col]);
            float b1 = __ldg(&bias[col + 1]);
            if (r0v < n) {
                float2 o = make_float2(acc[mt][nt][0] + b0, acc[mt][nt][1] + b1);
                *(float2*)&out[(size_t)r0v * 128 + col] = o;
            }
            if (r1v < n) {
                float2 o = make_float2(acc[mt][nt][2] + b0, acc[mt][nt][3] + b1);
                *(float2*)&out[(size_t)r1v * 128 + col] = o;
            }
        }
    }
}

// ---------------- bias combine ----------------
__global__ void bias_combine_kernel(const float* __restrict__ bd1, const float* __restrict__ bs1,
                                    const float* __restrict__ bu1, const float* __restrict__ Wu1,
                                    const float* __restrict__ bd2, const float* __restrict__ bs2,
                                    const float* __restrict__ bu2, const float* __restrict__ Wu2) {
    int layer = blockIdx.x >> 1;
    int which = blockIdx.x & 1;
    int h = threadIdx.x;
    const float* bd = layer ? bd2 : bd1;
    const float* bs = layer ? bs2 : bs1;
    const float* bu = layer ? bu2 : bu1;
    const float* Wu = layer ? Wu2 : Wu1;
    auto cfun = [&](int i) {
        float s = bu[i * 128 + h];
        const float* wt = Wu + (size_t)i * WU;
        for (int k = 0; k < 128; ++k) s = fmaf(bd[i * 128 + k], wt[k * 128 + h], s);
        const float* wb = wt + WUB;
        for (int k = 0; k < 128; ++k) s = fmaf(bs[i * 128 + k], wb[k * 128 + h], s);
        return s;
    };
    if (which == 0)
        d_bg[layer][h] = 0.5f * (cfun(0) + cfun(2));
    else
        d_bd[layer][h] = cfun(1);
}

// ---------------- batch norm ----------------
__global__ void bn_stats_kernel(const float* __restrict__ xg, const float* __restrict__ xd, int gb) {
    int c = threadIdx.x;
    bool gene = (int)blockIdx.x < gb;
    const float* x = gene ? xg : xd;
    int nn = gene ? NG : ND;
    int b = gene ? blockIdx.x : (blockIdx.x - gb);
    int r0 = b * 128;
    int rend = min(r0 + 128, nn);
    float s = 0.f, s2 = 0.f;
    for (int r = r0; r < rend; ++r) {
        float v = x[(size_t)r * 128 + c];
        s += v;
        s2 = fmaf(v, v, s2);
    }
    int off = gene ? 0 : 128;
    atomicAdd(&d_bn_acc[off + c], s);
    atomicAdd(&d_bn_acc[256 + off + c], s2);
}
__global__ void bn_final_kernel(const float* __restrict__ gamma, const float* __restrict__ beta) {
    int idx = blockIdx.x;
    int c = threadIdx.x;
    float nn = (idx == 0) ? (float)NG : (float)ND;
    float mean = d_bn_acc[idx * 128 + c] / nn;
    float var = d_bn_acc[256 + idx * 128 + c] / nn - mean * mean;
    float sc = gamma[idx * 128 + c] * rsqrtf(var + 1e-5f);
    d_bn_scale[idx][c] = sc;
    d_bn_shift[idx][c] = beta[idx * 128 + c] - mean * sc;
}
// BN + leaky relu -> hi/lo planes (overwrites x shadows; g1/d1 fp32 not written back)
__global__ void bn_apply_kernel(const float* __restrict__ xg, const float* __restrict__ xd) {
    int i = blockIdx.x * blockDim.x + threadIdx.x;
    int which;
    const float* x;
    __nv_bfloat16 *oh, *ol;
    if (i < NG * 32) { which = 0; x = xg; oh = d_xg_h; ol = d_xg_l; }
    else if (i < (NG + ND) * 32) { which = 1; x = xd; oh = d_xd_h; ol = d_xd_l; i -= NG * 32; }
    else return;
    int q = i & 31;
    int c = q * 4;
    const float* sc = d_bn_scale[which];
    const float* sh = d_bn_shift[which];
    float4 v = *(const float4*)&x[(size_t)i * 4];
    v.x = fmaf(v.x, sc[c + 0], sh[c + 0]);
    v.y = fmaf(v.y, sc[c + 1], sh[c + 1]);
    v.z = fmaf(v.z, sc[c + 2], sh[c + 2]);
    v.w = fmaf(v.w, sc[c + 3], sh[c + 3]);
    v.x = v.x >= 0.f ? v.x : 0.01f * v.x;
    v.y = v.y >= 0.f ? v.y : 0.01f * v.y;
    v.z = v.z >= 0.f ? v.z : 0.01f * v.z;
    v.w = v.w >= 0.f ? v.w : 0.01f * v.w;
    uint2 uh, ul;
    split2(v.x, v.y, uh.x, ul.x);
    split2(v.z, v.w, uh.y, ul.y);
    *(uint2*)&oh[(size_t)i * 4] = uh;
    *(uint2*)&ol[(size_t)i * 4] = ul;
}

// ---------------- decoder ----------------
__global__ void decode_kernel(const int* __restrict__ ls, const int* __restrict__ ld,
                              float* __restrict__ out) {
    int gw = (blockIdx.x * blockDim.x + threadIdx.x) >> 5;
    int lane = threadIdx.x & 31;
    if (gw >= ELAB) return;
    int a = __ldg(&ls[gw]);
    int b = __ldg(&ld[gw]);
    float4 u = *(const float4*)&d_g2[(size_t)a * 128 + lane * 4];
    float4 v = *(const float4*)&d_d2[(size_t)b * 128 + lane * 4];
    float s = u.x * v.x + u.y * v.y + u.z * v.z + u.w * v.w;
#pragma unroll
    for (int o = 16; o; o >>= 1) s += __shfl_xor_sync(0xFFFFFFFFu, s, o);
    if (lane == 0) out[gw] = s;
}

// ---------------- launch ----------------
static inline int cdiv(int a, int b) { return (a + b - 1) / b; }

extern "C" void kernel_launch(void* const* d_in, const int* in_sizes, int n_in,
                              void* d_out, int out_size) {
    const float* x_gene = (const float*)d_in[0];
    const float* x_dis  = (const float*)d_in[1];
    const float* W_dst1 = (const float*)d_in[2];
    const float* W_src1 = (const float*)d_in[3];
    const float* W_upd1 = (const float*)d_in[4];
    const float* b_dst1 = (const float*)d_in[5];
    const float* b_src1 = (const float*)d_in[6];
    const float* b_upd1 = (const float*)d_in[7];
    const float* W_dst2 = (const float*)d_in[8];
    const float* W_src2 = (const float*)d_in[9];
    const float* W_upd2 = (const float*)d_in[10];
    const float* b_dst2 = (const float*)d_in[11];
    const float* b_src2 = (const float*)d_in[12];
    const float* b_upd2 = (const float*)d_in[13];
    const float* bn_gamma = (const float*)d_in[14];
    const float* bn_beta  = (const float*)d_in[15];
    const int* gg_src  = (const int*)d_in[16];
    const int* gg_dst  = (const int*)d_in[17];
    const int* gda_src = (const int*)d_in[18];
    const int* gda_dst = (const int*)d_in[19];
    const int* label_src = (const int*)d_in[20];
    const int* label_dst = (const int*)d_in[21];
    float* out = (float*)d_out;

    static cudaStream_t s2 = nullptr;
    static cudaEvent_t e0 = nullptr, e1 = nullptr;
    if (!s2) {
        cudaFuncSetAttribute(mmagemm_kernel, cudaFuncAttributeMaxDynamicSharedMemorySize, SMEM_TOTAL);
        cudaStreamCreateWithFlags(&s2, cudaStreamNonBlocking);
        cudaEventCreateWithFlags(&e0, cudaEventDisableTiming);
        cudaEventCreateWithFlags(&e1, cudaEventDisableTiming);
    }

    float *g1, *d1, *g2, *d2, *bg, *bd;
    __nv_bfloat16 *Wh, *Wl;
    cudaGetSymbolAddress((void**)&g1, d_g1);
    cudaGetSymbolAddress((void**)&d1, d_d1);
    cudaGetSymbolAddress((void**)&g2, d_g2);
    cudaGetSymbolAddress((void**)&d2, d_d2);
    cudaGetSymbolAddress((void**)&Wh, d_Wh);
    cudaGetSymbolAddress((void**)&Wl, d_Wl);
    cudaGetSymbolAddress((void**)&bg, d_bg);
    cudaGetSymbolAddress((void**)&bd, d_bd);

    const int GB = cdiv(NG, 128), DB = cdiv(ND, 128);

    // fork: side stream does input conversion + weight prep while main builds CSR
    cudaEventRecord(e0, 0);
    cudaStreamWaitEvent(s2, e0, 0);
    tobf16_kernel<<<cdiv((NG + ND) * 32, 256), 256, 0, s2>>>(x_gene, x_dis);
    wprep_kernel<<<10, 256, 0, s2>>>(W_dst1, W_src1, W_upd1, W_dst2, W_src2, W_upd2, Wh, Wl);
    bias_combine_kernel<<<4, 128, 0, s2>>>(b_dst1, b_src1, b_upd1, W_upd1,
                                           b_dst2, b_src2, b_upd2, W_upd2);
    cudaEventRecord(e1, s2);

    // main: CSR build
    init_kernel<<<cdiv(NTOT + 512, 256), 256>>>();
    deg_all_kernel<<<cdiv(ETOT, 256), 256>>>(gg_dst, gda_dst, gda_src);
    scan_all_kernel<<<3, 1024>>>();
    fill_all_kernel<<<cdiv(ETOT, 256), 256>>>(gg_src, gg_dst, gda_src, gda_dst);

    // join
    cudaStreamWaitEvent(0, e1, 0);

    // layer-1 aggregation + GEMM
    gather_all_kernel<<<cdiv(NTOT * 32, 256), 256>>>();
    mmagemm_kernel<<<GB + DB, 256, SMEM_TOTAL>>>(Wh, Wl, bg, bd, g1, d1, GB);

    // BN + leaky relu (apply emits hi/lo planes into x shadows)
    bn_stats_kernel<<<GB + DB, 128>>>(g1, d1, GB);
    bn_final_kernel<<<2, 128>>>(bn_gamma, bn_beta);
    bn_apply_kernel<<<cdiv((NG + ND) * 32, 256), 256>>>(g1, d1);

    // layer-2 aggregation + GEMM
    gather_all_kernel<<<cdiv(NTOT * 32, 256), 256>>>();
    mmagemm_kernel<<<GB + DB, 256, SMEM_TOTAL>>>(Wh + 5 * MM, Wl + 5 * MM,
                                                 bg + HD, bd + HD, g2, d2, GB);

    // decoder
    decode_kernel<<<cdiv(ELAB * 32, 256), 256>>>(label_src, label_dst, out);
}